// round 13
// baseline (speedup 1.0000x reference)
#include <cuda_runtime.h>
#include <cuda_bf16.h>
#include <math.h>
#include <stdint.h>

#define BB 8
#define NN 2048
#define DD 384
#define CP 64
#define NF 10

__device__ float g_M [CP * CP];
__device__ __nv_bfloat16 g_Wvh[DD * CP];
__device__ __nv_bfloat16 g_Wvl[DD * CP];
__device__ __nv_bfloat16 g_An_hi[BB * NN * CP];
__device__ __nv_bfloat16 g_An_lo[BB * NN * CP];
__device__ __nv_bfloat16 g_U_hi [BB * NN * CP];
__device__ __nv_bfloat16 g_U_lo [BB * NN * CP];
__device__ __nv_bfloat16 g_Bk_hi[BB * CP * NN];
__device__ __nv_bfloat16 g_Bk_lo[BB * CP * NN];

__device__ __forceinline__ uint32_t smem_u32(const void* p) {
    uint32_t a;
    asm("{ .reg .u64 t; cvta.to.shared.u64 t, %1; cvt.u32.u64 %0, t; }" : "=r"(a) : "l"(p));
    return a;
}
__device__ __forceinline__ void cp16(uint32_t dst, const void* src) {
    asm volatile("cp.async.cg.shared.global [%0], [%1], 16;" :: "r"(dst), "l"(src));
}
#define CP_COMMIT() asm volatile("cp.async.commit_group;" ::: "memory")
#define CP_WAIT0()  asm volatile("cp.async.wait_group 0;" ::: "memory")

__device__ __forceinline__ uint32_t cvt2(float hi, float lo) {
    uint32_t r; asm("cvt.rn.bf16x2.f32 %0, %1, %2;" : "=r"(r) : "f"(hi), "f"(lo)); return r;
}
__device__ __forceinline__ void mma16816(float* d, const uint32_t* a, const uint32_t* b) {
    asm volatile("mma.sync.aligned.m16n8k16.row.col.f32.bf16.bf16.f32 "
        "{%0,%1,%2,%3}, {%4,%5,%6,%7}, {%8,%9}, {%0,%1,%2,%3};"
        : "+f"(d[0]), "+f"(d[1]), "+f"(d[2]), "+f"(d[3])
        : "r"(a[0]), "r"(a[1]), "r"(a[2]), "r"(a[3]), "r"(b[0]), "r"(b[1]));
}

// ---------------- 1. prep: M' (tiled GEMM, 1 block) + Wv' split ----------------
#define WBLK ((DD * CP + 255) / 256)
__global__ void __launch_bounds__(256) prep_kernel(
        const float* __restrict__ Wq, const float* __restrict__ bq,
        const float* __restrict__ Wk, const float* __restrict__ bk,
        const float* __restrict__ Wv, const float* __restrict__ bv) {
    int t = threadIdx.x;
    if (blockIdx.x == 0) {
        __shared__ float sq[64][64];
        __shared__ float sk[64][64];
        int ti = t & 15, tj = t >> 4;
        int i0 = ti * 4, j0 = tj * 4;
        float creg[4][4];
#pragma unroll
        for (int x = 0; x < 4; x++)
#pragma unroll
            for (int y = 0; y < 4; y++) creg[x][y] = 0.0f;
        for (int kc = 0; kc < 6; kc++) {
#pragma unroll
            for (int j = 0; j < 16; j++) {
                int idx = t + j * 256;
                int r = idx >> 6, c = idx & 63;
                int d = kc * 64 + r;
                sq[r][c] = (c < 60) ? Wq[d * 60 + c] : ((c == 60) ? bq[d] : 0.0f);
                sk[r][c] = (c < 60) ? Wk[d * 60 + c] : ((c == 60) ? bk[d] : 0.0f);
            }
            __syncthreads();
#pragma unroll 8
            for (int r = 0; r < 64; r++) {
                float a[4], bb2[4];
#pragma unroll
                for (int x = 0; x < 4; x++) { a[x] = sq[r][i0 + x]; bb2[x] = sk[r][j0 + x]; }
#pragma unroll
                for (int x = 0; x < 4; x++)
#pragma unroll
                    for (int y = 0; y < 4; y++) creg[x][y] = fmaf(a[x], bb2[y], creg[x][y]);
            }
            __syncthreads();
        }
        float scale = sqrtf((float)DD);
#pragma unroll
        for (int x = 0; x < 4; x++)
#pragma unroll
            for (int y = 0; y < 4; y++)
                g_M[(i0 + x) * CP + j0 + y] = creg[x][y] * scale;
    } else {
        int r = (blockIdx.x - 1) * 256 + t;
        if (r < DD * CP) {
            int d = r / CP, c = r % CP;
            float v = (c < 60) ? Wv[d * 60 + c] : ((c == 60) ? bv[d] : 0.0f);
            __nv_bfloat16 h = __float2bfloat16(v);
            g_Wvh[r] = h;
            g_Wvl[r] = __float2bfloat16(v - __bfloat162float(h));
        }
    }
}

// ---------------- 2. fused pe + splits + u-GEMM ----------------
#define BSP 132
__global__ void __launch_bounds__(256) pe_u_kernel(const float* __restrict__ pos) {
    __shared__ float Ms[64][64];
    __shared__ float Bs[64][BSP];
    int b = blockIdx.y, n0 = blockIdx.x * 128, t = threadIdx.x;

#pragma unroll
    for (int j = 0; j < 4; j++) {
        int idx = t + j * 256, row = idx >> 4, c4 = idx & 15;
        *reinterpret_cast<float4*>(&Ms[row][c4 * 4]) =
            *reinterpret_cast<const float4*>(g_M + row * CP + c4 * 4);
    }
    {
        int tok = t >> 1, half = t & 1, n = n0 + tok;
        float x0 = pos[(size_t)b * 3 * NN + n];
        float x1 = pos[(size_t)b * 3 * NN + NN + n];
        float x2 = pos[(size_t)b * 3 * NN + 2 * NN + n];
#pragma unroll
        for (int pp = 0; pp < 15; pp++) {
            int p = 15 * half + pp;
            int coord = p / 10, k = p - coord * 10;
            float x = (coord == 0) ? x0 : ((coord == 1) ? x1 : x2);
            float s, c;
            sincosf(x * (float)(1 << k), &s, &c);
            Bs[coord * 20 + k][tok]      = s;
            Bs[coord * 20 + 10 + k][tok] = c;
        }
        if (half) {
            Bs[60][tok] = 1.0f; Bs[61][tok] = 0.0f;
            Bs[62][tok] = 0.0f; Bs[63][tok] = 0.0f;
        }
    }
    __syncthreads();

    {
        int tk = t & 127, which = t >> 7;
        __nv_bfloat16 tmp[64];
        if (which == 0) {
#pragma unroll
            for (int c = 0; c < 64; c++) tmp[c] = __float2bfloat16(Bs[c][tk]);
        } else {
#pragma unroll
            for (int c = 0; c < 64; c++) {
                float x = Bs[c][tk];
                __nv_bfloat16 h = __float2bfloat16(x);
                tmp[c] = __float2bfloat16(x - __bfloat162float(h));
            }
        }
        float4* d = (float4*)((which ? g_An_lo : g_An_hi) + ((size_t)b * NN + n0 + tk) * CP);
#pragma unroll
        for (int j = 0; j < 8; j++) d[j] = ((float4*)tmp)[j];
    }

#pragma unroll
    for (int j = 0; j < 16; j++) {
        int idx = t + j * 256;
        int ch = idx >> 6, tp = idx & 63;
        float2 v = *reinterpret_cast<float2*>(&Bs[ch][tp * 2]);
        uint32_t hw = cvt2(v.y, v.x);
        float h0 = __uint_as_float(hw << 16);
        float h1 = __uint_as_float(hw & 0xffff0000u);
        uint32_t lw = cvt2(v.y - h1, v.x - h0);
        *reinterpret_cast<uint32_t*>(g_Bk_hi + ((size_t)b * CP + ch) * NN + n0 + tp * 2) = hw;
        *reinterpret_cast<uint32_t*>(g_Bk_lo + ((size_t)b * CP + ch) * NN + n0 + tp * 2) = lw;
    }

    int tx = t & 15, ty = t >> 4;
    float acc[4][8];
#pragma unroll
    for (int j = 0; j < 4; j++)
#pragma unroll
        for (int k = 0; k < 8; k++) acc[j][k] = 0.0f;
#pragma unroll 8
    for (int c = 0; c < 64; c++) {
        float a[4];
#pragma unroll
        for (int j = 0; j < 4; j++) a[j] = Ms[ty * 4 + j][c];
        float4 b0 = *reinterpret_cast<float4*>(&Bs[c][tx * 8]);
        float4 b1 = *reinterpret_cast<float4*>(&Bs[c][tx * 8 + 4]);
        float bb[8] = {b0.x, b0.y, b0.z, b0.w, b1.x, b1.y, b1.z, b1.w};
#pragma unroll
        for (int j = 0; j < 4; j++)
#pragma unroll
            for (int k = 0; k < 8; k++) acc[j][k] = fmaf(a[j], bb[k], acc[j][k]);
    }
#pragma unroll
    for (int k = 0; k < 8; k++) {
        size_t m = (size_t)b * NN + n0 + tx * 8 + k;
        uint32_t h01 = cvt2(acc[1][k], acc[0][k]);
        uint32_t h23 = cvt2(acc[3][k], acc[2][k]);
        float f0 = __uint_as_float(h01 << 16), f1 = __uint_as_float(h01 & 0xffff0000u);
        float f2 = __uint_as_float(h23 << 16), f3 = __uint_as_float(h23 & 0xffff0000u);
        uint32_t l01 = cvt2(acc[1][k] - f1, acc[0][k] - f0);
        uint32_t l23 = cvt2(acc[3][k] - f3, acc[2][k] - f2);
        *reinterpret_cast<uint2*>(g_U_hi + m * CP + ty * 4) = make_uint2(h01, h23);
        *reinterpret_cast<uint2*>(g_U_lo + m * CP + ty * 4) = make_uint2(l01, l23);
    }
}

// ---------------- 3. fused flash attention + output GEMM ----------------
// 64 q-rows per block, 128 threads, single-stage smem (90KB) -> 2 blocks/SM.
#define PITA 144
#define PITK 272
#define SM_APEH 0
#define SM_APEL 9216
#define SM_STG  18432
#define OFF_UL  18432
#define OFF_KH  36864
#define OFF_KL  54272
#define SSTR    71680
#define SM_TOT  (SM_STG + SSTR)         // 90112
#define WV_LO   27648                   // within stage: 192 rows * 144

__global__ void __launch_bounds__(128, 2) fused_attn_mma(float* __restrict__ Out) {
    extern __shared__ char smc[];
    uint32_t sb = smem_u32(smc);
    const int t = threadIdx.x, w = t >> 5, lane = t & 31;
    const int g = lane >> 2, tg = lane & 3;
    const int b = blockIdx.y, n0 = blockIdx.x * 64;

    // APE tile: 64 rows
    {
        const float4* sh = (const float4*)(g_An_hi + ((size_t)b * NN + n0) * CP);
        const float4* sl = (const float4*)(g_An_lo + ((size_t)b * NN + n0) * CP);
#pragma unroll
        for (int j = 0; j < 4; j++) {
            int li = t + j * 128, row = li >> 3, ch = li & 7;
            *(float4*)(smc + SM_APEH + row * PITA + ch * 16) = sh[li];
            *(float4*)(smc + SM_APEL + row * PITA + ch * 16) = sl[li];
        }
    }

    float zacc[8][4];
#pragma unroll
    for (int cf = 0; cf < 8; cf++)
#pragma unroll
        for (int e = 0; e < 4; e++) zacc[cf][e] = 0.0f;
    float mrun0 = -1e30f, mrun1 = -1e30f, lrun0 = 0.0f, lrun1 = 0.0f;

    for (int mt = 0; mt < 16; mt++) {
        int m0 = mt * 128;
        {
            uint32_t ub = sb + SM_STG;
#pragma unroll
            for (int j = 0; j < 8; j++) {
                int li = t + j * 128, row = li >> 3, ch = li & 7;
                cp16(ub + row * PITA + ch * 16,
                     g_U_hi + ((size_t)b * NN + m0 + row) * CP + ch * 8);
                cp16(ub + OFF_UL + row * PITA + ch * 16,
                     g_U_lo + ((size_t)b * NN + m0 + row) * CP + ch * 8);
            }
#pragma unroll
            for (int j = 0; j < 8; j++) {
                int li = t + j * 128, row = li >> 4, ch = li & 15;
                cp16(ub + OFF_KH + row * PITK + ch * 16,
                     g_Bk_hi + (size_t)(b * CP + row) * NN + m0 + ch * 8);
                cp16(ub + OFF_KL + row * PITK + ch * 16,
                     g_Bk_lo + (size_t)(b * CP + row) * NN + m0 + ch * 8);
            }
        }
        CP_COMMIT();
        CP_WAIT0();
        __syncthreads();

        const char* UB = smc + SM_STG;

        float sfr[16][4];
#pragma unroll
        for (int mf = 0; mf < 16; mf++)
#pragma unroll
            for (int e = 0; e < 4; e++) sfr[mf][e] = 0.0f;

#pragma unroll
        for (int ks = 0; ks < 4; ks++) {
            uint32_t abase = (uint32_t)((w * 16 + g) * PITA + (ks * 16 + tg * 2) * 2);
            uint32_t ah[4], al_[4];
            ah[0]  = *(const uint32_t*)(smc + SM_APEH + abase);
            ah[1]  = *(const uint32_t*)(smc + SM_APEH + abase + 8 * PITA);
            ah[2]  = *(const uint32_t*)(smc + SM_APEH + abase + 16);
            ah[3]  = *(const uint32_t*)(smc + SM_APEH + abase + 8 * PITA + 16);
            al_[0] = *(const uint32_t*)(smc + SM_APEL + abase);
            al_[1] = *(const uint32_t*)(smc + SM_APEL + abase + 8 * PITA);
            al_[2] = *(const uint32_t*)(smc + SM_APEL + abase + 16);
            al_[3] = *(const uint32_t*)(smc + SM_APEL + abase + 8 * PITA + 16);
#pragma unroll
            for (int mf = 0; mf < 16; mf++) {
                uint32_t bbase = (uint32_t)((mf * 8 + g) * PITA + (ks * 16 + tg * 2) * 2);
                uint32_t bh[2] = { *(const uint32_t*)(UB + bbase),
                                   *(const uint32_t*)(UB + bbase + 16) };
                uint32_t bl[2] = { *(const uint32_t*)(UB + OFF_UL + bbase),
                                   *(const uint32_t*)(UB + OFF_UL + bbase + 16) };
                mma16816(sfr[mf], ah, bh);
                mma16816(sfr[mf], ah, bl);
                mma16816(sfr[mf], al_, bh);
            }
        }

        float tm0 = -1e30f, tm1 = -1e30f;
#pragma unroll
        for (int mf = 0; mf < 16; mf++) {
            tm0 = fmaxf(tm0, fmaxf(sfr[mf][0], sfr[mf][1]));
            tm1 = fmaxf(tm1, fmaxf(sfr[mf][2], sfr[mf][3]));
        }
        tm0 = fmaxf(tm0, __shfl_xor_sync(0xffffffffu, tm0, 1));
        tm0 = fmaxf(tm0, __shfl_xor_sync(0xffffffffu, tm0, 2));
        tm1 = fmaxf(tm1, __shfl_xor_sync(0xffffffffu, tm1, 1));
        tm1 = fmaxf(tm1, __shfl_xor_sync(0xffffffffu, tm1, 2));
        float nm0 = fmaxf(mrun0, tm0), nm1 = fmaxf(mrun1, tm1);
        float al0 = __expf(mrun0 - nm0), al1 = __expf(mrun1 - nm1);
        mrun0 = nm0; mrun1 = nm1;
#pragma unroll
        for (int cf = 0; cf < 8; cf++) {
            zacc[cf][0] *= al0; zacc[cf][1] *= al0;
            zacc[cf][2] *= al1; zacc[cf][3] *= al1;
        }
        lrun0 *= al0; lrun1 *= al1;

        uint32_t ph[16][2], pl[16][2];
        float rs0 = 0.0f, rs1 = 0.0f;
#pragma unroll
        for (int mf = 0; mf < 16; mf++) {
            float p0 = __expf(sfr[mf][0] - nm0), p1 = __expf(sfr[mf][1] - nm0);
            float p2 = __expf(sfr[mf][2] - nm1), p3 = __expf(sfr[mf][3] - nm1);
            rs0 += p0 + p1; rs1 += p2 + p3;
            uint32_t h01 = cvt2(p1, p0);
            uint32_t h23 = cvt2(p3, p2);
            ph[mf][0] = h01; ph[mf][1] = h23;
            float f0 = __uint_as_float(h01 << 16), f1 = __uint_as_float(h01 & 0xffff0000u);
            float f2 = __uint_as_float(h23 << 16), f3 = __uint_as_float(h23 & 0xffff0000u);
            pl[mf][0] = cvt2(p1 - f1, p0 - f0);
            pl[mf][1] = cvt2(p3 - f3, p2 - f2);
        }
        rs0 += __shfl_xor_sync(0xffffffffu, rs0, 1);
        rs0 += __shfl_xor_sync(0xffffffffu, rs0, 2);
        rs1 += __shfl_xor_sync(0xffffffffu, rs1, 1);
        rs1 += __shfl_xor_sync(0xffffffffu, rs1, 2);
        lrun0 += rs0; lrun1 += rs1;

#pragma unroll
        for (int ks = 0; ks < 8; ks++) {
            uint32_t aph[4] = { ph[2 * ks][0], ph[2 * ks][1], ph[2 * ks + 1][0], ph[2 * ks + 1][1] };
            uint32_t apl[4] = { pl[2 * ks][0], pl[2 * ks][1], pl[2 * ks + 1][0], pl[2 * ks + 1][1] };
#pragma unroll
            for (int cf = 0; cf < 8; cf++) {
                uint32_t bb = (uint32_t)((cf * 8 + g) * PITK + (ks * 16 + tg * 2) * 2);
                uint32_t kh[2] = { *(const uint32_t*)(UB + OFF_KH + bb),
                                   *(const uint32_t*)(UB + OFF_KH + bb + 16) };
                uint32_t kl[2] = { *(const uint32_t*)(UB + OFF_KL + bb),
                                   *(const uint32_t*)(UB + OFF_KL + bb + 16) };
                mma16816(zacc[cf], aph, kh);
                mma16816(zacc[cf], apl, kh);
                mma16816(zacc[cf], aph, kl);
            }
        }
        __syncthreads();
    }

    // ---- epilogue: write normalized Z (bf16 hi/lo) into APE area, then
    //      out[:, n0:n0+64] = Wv' * Z in two 192-row phases ----
    {
        float inv0 = 1.0f / lrun0, inv1 = 1.0f / lrun1;
        int r0 = w * 16 + g;
#pragma unroll
        for (int cf = 0; cf < 8; cf++) {
            int cb = cf * 16 + tg * 4;
            float v0 = zacc[cf][0] * inv0, v1 = zacc[cf][1] * inv0;
            float v2 = zacc[cf][2] * inv1, v3 = zacc[cf][3] * inv1;
            uint32_t h01 = cvt2(v1, v0), h23 = cvt2(v3, v2);
            float f0 = __uint_as_float(h01 << 16), f1 = __uint_as_float(h01 & 0xffff0000u);
            float f2 = __uint_as_float(h23 << 16), f3 = __uint_as_float(h23 & 0xffff0000u);
            *(uint32_t*)(smc + SM_APEH + r0 * PITA + cb)       = h01;
            *(uint32_t*)(smc + SM_APEL + r0 * PITA + cb)       = cvt2(v1 - f1, v0 - f0);
            *(uint32_t*)(smc + SM_APEH + (r0 + 8) * PITA + cb) = h23;
            *(uint32_t*)(smc + SM_APEL + (r0 + 8) * PITA + cb) = cvt2(v3 - f3, v2 - f2);
        }
    }

    float* Op = Out + (size_t)b * DD * NN;
#pragma unroll
    for (int p = 0; p < 2; p++) {
        // load Wv' rows [192p, 192p+192) hi/lo into stage
        {
            uint32_t wb = sb + SM_STG;
#pragma unroll
            for (int j = 0; j < 12; j++) {
                int li = t + j * 128, row = li >> 3, ch = li & 7;
                cp16(wb + row * PITA + ch * 16,
                     g_Wvh + (size_t)(p * 192 + row) * CP + ch * 8);
                cp16(wb + WV_LO + row * PITA + ch * 16,
                     g_Wvl + (size_t)(p * 192 + row) * CP + ch * 8);
            }
        }
        CP_COMMIT();
        CP_WAIT0();
        __syncthreads();            // Wv ready; Z writes visible (first iter)

#pragma unroll
        for (int df = 0; df < 3; df++) {
            float acc[8][4];
#pragma unroll
            for (int nf = 0; nf < 8; nf++)
#pragma unroll
                for (int e = 0; e < 4; e++) acc[nf][e] = 0.0f;

#pragma unroll
            for (int ks = 0; ks < 4; ks++) {
                uint32_t abase = (uint32_t)((df * 64 + w * 16 + g) * PITA + (ks * 16 + tg * 2) * 2);
                uint32_t ah[4], al_[4];
                ah[0]  = *(const uint32_t*)(smc + SM_STG + abase);
                ah[1]  = *(const uint32_t*)(smc + SM_STG + abase + 8 * PITA);
                ah[2]  = *(const uint32_t*)(smc + SM_STG + abase + 16);
                ah[3]  = *(const uint32_t*)(smc + SM_STG + abase + 8 * PITA + 16);
                al_[0] = *(const uint32_t*)(smc + SM_STG + WV_LO + abase);
                al_[1] = *(const uint32_t*)(smc + SM_STG + WV_LO + abase + 8 * PITA);
                al_[2] = *(const uint32_t*)(smc + SM_STG + WV_LO + abase + 16);
                al_[3] = *(const uint32_t*)(smc + SM_STG + WV_LO + abase + 8 * PITA + 16);
#pragma unroll
                for (int nf = 0; nf < 8; nf++) {
                    uint32_t bbase = (uint32_t)((nf * 8 + g) * PITA + (ks * 16 + tg * 2) * 2);
                    uint32_t bh[2] = { *(const uint32_t*)(smc + SM_APEH + bbase),
                                       *(const uint32_t*)(smc + SM_APEH + bbase + 16) };
                    uint32_t bl[2] = { *(const uint32_t*)(smc + SM_APEL + bbase),
                                       *(const uint32_t*)(smc + SM_APEL + bbase + 16) };
                    mma16816(acc[nf], ah, bh);
                    mma16816(acc[nf], ah, bl);
                    mma16816(acc[nf], al_, bh);
                }
            }

            int dd0 = p * 192 + df * 64 + w * 16 + g, dd1 = dd0 + 8;
#pragma unroll
            for (int nf = 0; nf < 8; nf++) {
                int n = n0 + nf * 8 + tg * 2;
                *reinterpret_cast<float2*>(Op + (size_t)dd0 * NN + n) = make_float2(acc[nf][0], acc[nf][1]);
                *reinterpret_cast<float2*>(Op + (size_t)dd1 * NN + n) = make_float2(acc[nf][2], acc[nf][3]);
            }
        }
        __syncthreads();            // all reads of this Wv phase done before reload
    }
}

// ---------------------------------------------------------------------------
extern "C" void kernel_launch(void* const* d_in, const int* in_sizes, int n_in,
                              void* d_out, int out_size) {
    const float* pos = (const float*)d_in[0];
    const float* Wq  = (const float*)d_in[1];
    const float* bq  = (const float*)d_in[2];
    const float* Wk  = (const float*)d_in[3];
    const float* bk  = (const float*)d_in[4];
    const float* Wv  = (const float*)d_in[5];
    const float* bv  = (const float*)d_in[6];
    float* out = (float*)d_out;

    prep_kernel<<<1 + WBLK, 256>>>(Wq, bq, Wk, bk, Wv, bv);
    pe_u_kernel<<<dim3(NN / 128, BB), 256>>>(pos);

    cudaFuncSetAttribute(fused_attn_mma, cudaFuncAttributeMaxDynamicSharedMemorySize, SM_TOT);
    fused_attn_mma<<<dim3(NN / 64, BB), 128, SM_TOT>>>(out);
}

// round 14
// speedup vs baseline: 2.3009x; 2.3009x over previous
#include <cuda_runtime.h>
#include <cuda_bf16.h>
#include <math.h>
#include <stdint.h>

#define BB 8
#define NN 2048
#define DD 384
#define CP 64
#define NF 10

__device__ float g_M [CP * CP];
__device__ __nv_bfloat16 g_Wvh[DD * CP];
__device__ __nv_bfloat16 g_Wvl[DD * CP];
__device__ __nv_bfloat16 g_An_hi[BB * NN * CP];
__device__ __nv_bfloat16 g_An_lo[BB * NN * CP];
__device__ __nv_bfloat16 g_U_hi [BB * NN * CP];
__device__ __nv_bfloat16 g_U_lo [BB * NN * CP];
__device__ __nv_bfloat16 g_Bk_hi[BB * CP * NN];
__device__ __nv_bfloat16 g_Bk_lo[BB * CP * NN];
__device__ __nv_bfloat16 g_Zh[BB * NN * CP];
__device__ __nv_bfloat16 g_Zl[BB * NN * CP];

__device__ __forceinline__ uint32_t smem_u32(const void* p) {
    uint32_t a;
    asm("{ .reg .u64 t; cvta.to.shared.u64 t, %1; cvt.u32.u64 %0, t; }" : "=r"(a) : "l"(p));
    return a;
}
__device__ __forceinline__ void cp16(uint32_t dst, const void* src) {
    asm volatile("cp.async.cg.shared.global [%0], [%1], 16;" :: "r"(dst), "l"(src));
}
#define CP_COMMIT() asm volatile("cp.async.commit_group;" ::: "memory")
#define CP_WAIT1()  asm volatile("cp.async.wait_group 1;" ::: "memory")
#define CP_WAIT0()  asm volatile("cp.async.wait_group 0;" ::: "memory")

__device__ __forceinline__ uint32_t cvt2(float hi, float lo) {
    uint32_t r; asm("cvt.rn.bf16x2.f32 %0, %1, %2;" : "=r"(r) : "f"(hi), "f"(lo)); return r;
}
__device__ __forceinline__ void mma16816(float* d, const uint32_t* a, const uint32_t* b) {
    asm volatile("mma.sync.aligned.m16n8k16.row.col.f32.bf16.bf16.f32 "
        "{%0,%1,%2,%3}, {%4,%5,%6,%7}, {%8,%9}, {%0,%1,%2,%3};"
        : "+f"(d[0]), "+f"(d[1]), "+f"(d[2]), "+f"(d[3])
        : "r"(a[0]), "r"(a[1]), "r"(a[2]), "r"(a[3]), "r"(b[0]), "r"(b[1]));
}

// ---------------- 1. prep: M' (warp per 4x4 tile) + Wv' split ----------------
#define MTBLK 32                          // 32 blocks * 8 warps = 256 warps = 16x16 tiles
#define WBLK ((DD * CP + 255) / 256)
__global__ void __launch_bounds__(256) prep_kernel(
        const float* __restrict__ Wq, const float* __restrict__ bq,
        const float* __restrict__ Wk, const float* __restrict__ bk,
        const float* __restrict__ Wv, const float* __restrict__ bv) {
    int t = threadIdx.x;
    if (blockIdx.x < MTBLK) {
        int w = blockIdx.x * 8 + (t >> 5);
        int wi = w >> 4, wj = w & 15;     // 4x4 tile at (wi*4, wj*4)
        int l = t & 31;
        float acc[4][4];
#pragma unroll
        for (int x = 0; x < 4; x++)
#pragma unroll
            for (int y = 0; y < 4; y++) acc[x][y] = 0.0f;
#pragma unroll
        for (int it = 0; it < 12; it++) {
            int d = l + it * 32;
            float aq[4], ak[4];
#pragma unroll
            for (int x = 0; x < 4; x++) {
                int i = wi * 4 + x;
                aq[x] = (i < 60) ? Wq[d * 60 + i] : ((i == 60) ? bq[d] : 0.0f);
                int j = wj * 4 + x;
                ak[x] = (j < 60) ? Wk[d * 60 + j] : ((j == 60) ? bk[d] : 0.0f);
            }
#pragma unroll
            for (int x = 0; x < 4; x++)
#pragma unroll
                for (int y = 0; y < 4; y++) acc[x][y] = fmaf(aq[x], ak[y], acc[x][y]);
        }
        float scale = sqrtf((float)DD);
#pragma unroll
        for (int x = 0; x < 4; x++)
#pragma unroll
            for (int y = 0; y < 4; y++) {
                float v = acc[x][y];
#pragma unroll
                for (int s = 16; s > 0; s >>= 1) v += __shfl_xor_sync(0xffffffffu, v, s);
                if (l == 0) g_M[(wi * 4 + x) * CP + wj * 4 + y] = v * scale;
            }
    } else {
        int r = (blockIdx.x - MTBLK) * 256 + t;
        if (r < DD * CP) {
            int d = r / CP, c = r % CP;
            float v = (c < 60) ? Wv[d * 60 + c] : ((c == 60) ? bv[d] : 0.0f);
            __nv_bfloat16 h = __float2bfloat16(v);
            g_Wvh[r] = h;
            g_Wvl[r] = __float2bfloat16(v - __bfloat162float(h));
        }
    }
}

// ---------------- 2. fused pe + splits + u-GEMM ----------------
#define BSP 132
__global__ void __launch_bounds__(256) pe_u_kernel(const float* __restrict__ pos) {
    __shared__ float Ms[64][64];
    __shared__ float Bs[64][BSP];
    int b = blockIdx.y, n0 = blockIdx.x * 128, t = threadIdx.x;

#pragma unroll
    for (int j = 0; j < 4; j++) {
        int idx = t + j * 256, row = idx >> 4, c4 = idx & 15;
        *reinterpret_cast<float4*>(&Ms[row][c4 * 4]) =
            *reinterpret_cast<const float4*>(g_M + row * CP + c4 * 4);
    }
    {
        int tok = t >> 1, half = t & 1, n = n0 + tok;
        float x0 = pos[(size_t)b * 3 * NN + n];
        float x1 = pos[(size_t)b * 3 * NN + NN + n];
        float x2 = pos[(size_t)b * 3 * NN + 2 * NN + n];
#pragma unroll
        for (int pp = 0; pp < 15; pp++) {
            int p = 15 * half + pp;
            int coord = p / 10, k = p - coord * 10;
            float x = (coord == 0) ? x0 : ((coord == 1) ? x1 : x2);
            float s, c;
            sincosf(x * (float)(1 << k), &s, &c);
            Bs[coord * 20 + k][tok]      = s;
            Bs[coord * 20 + 10 + k][tok] = c;
        }
        if (half) {
            Bs[60][tok] = 1.0f; Bs[61][tok] = 0.0f;
            Bs[62][tok] = 0.0f; Bs[63][tok] = 0.0f;
        }
    }
    __syncthreads();

    {
        int tk = t & 127, which = t >> 7;
        __nv_bfloat16 tmp[64];
        if (which == 0) {
#pragma unroll
            for (int c = 0; c < 64; c++) tmp[c] = __float2bfloat16(Bs[c][tk]);
        } else {
#pragma unroll
            for (int c = 0; c < 64; c++) {
                float x = Bs[c][tk];
                __nv_bfloat16 h = __float2bfloat16(x);
                tmp[c] = __float2bfloat16(x - __bfloat162float(h));
            }
        }
        float4* d = (float4*)((which ? g_An_lo : g_An_hi) + ((size_t)b * NN + n0 + tk) * CP);
#pragma unroll
        for (int j = 0; j < 8; j++) d[j] = ((float4*)tmp)[j];
    }

#pragma unroll
    for (int j = 0; j < 16; j++) {
        int idx = t + j * 256;
        int ch = idx >> 6, tp = idx & 63;
        float2 v = *reinterpret_cast<float2*>(&Bs[ch][tp * 2]);
        uint32_t hw = cvt2(v.y, v.x);
        float h0 = __uint_as_float(hw << 16);
        float h1 = __uint_as_float(hw & 0xffff0000u);
        uint32_t lw = cvt2(v.y - h1, v.x - h0);
        *reinterpret_cast<uint32_t*>(g_Bk_hi + ((size_t)b * CP + ch) * NN + n0 + tp * 2) = hw;
        *reinterpret_cast<uint32_t*>(g_Bk_lo + ((size_t)b * CP + ch) * NN + n0 + tp * 2) = lw;
    }

    int tx = t & 15, ty = t >> 4;
    float acc[4][8];
#pragma unroll
    for (int j = 0; j < 4; j++)
#pragma unroll
        for (int k = 0; k < 8; k++) acc[j][k] = 0.0f;
#pragma unroll 8
    for (int c = 0; c < 64; c++) {
        float a[4];
#pragma unroll
        for (int j = 0; j < 4; j++) a[j] = Ms[ty * 4 + j][c];
        float4 b0 = *reinterpret_cast<float4*>(&Bs[c][tx * 8]);
        float4 b1 = *reinterpret_cast<float4*>(&Bs[c][tx * 8 + 4]);
        float bb[8] = {b0.x, b0.y, b0.z, b0.w, b1.x, b1.y, b1.z, b1.w};
#pragma unroll
        for (int j = 0; j < 4; j++)
#pragma unroll
            for (int k = 0; k < 8; k++) acc[j][k] = fmaf(a[j], bb[k], acc[j][k]);
    }
#pragma unroll
    for (int k = 0; k < 8; k++) {
        size_t m = (size_t)b * NN + n0 + tx * 8 + k;
        uint32_t h01 = cvt2(acc[1][k], acc[0][k]);
        uint32_t h23 = cvt2(acc[3][k], acc[2][k]);
        float f0 = __uint_as_float(h01 << 16), f1 = __uint_as_float(h01 & 0xffff0000u);
        float f2 = __uint_as_float(h23 << 16), f3 = __uint_as_float(h23 & 0xffff0000u);
        uint32_t l01 = cvt2(acc[1][k] - f1, acc[0][k] - f0);
        uint32_t l23 = cvt2(acc[3][k] - f3, acc[2][k] - f2);
        *reinterpret_cast<uint2*>(g_U_hi + m * CP + ty * 4) = make_uint2(h01, h23);
        *reinterpret_cast<uint2*>(g_U_lo + m * CP + ty * 4) = make_uint2(l01, l23);
    }
}

// ---------------- 3. mma.sync fused flash attention (R10 config) ----------------
#define PITA 144
#define PITK 272
#define SM_APEH 0
#define SM_APEL 18432
#define SM_STG  36864
#define OFF_UL  18432
#define OFF_KH  36864
#define OFF_KL  54272
#define SSTR    71680
#define SM_TOT  (SM_STG + 2 * SSTR)

__global__ void __launch_bounds__(256, 1) fused_attn_mma() {
    extern __shared__ char smc[];
    uint32_t sb = smem_u32(smc);
    const int t = threadIdx.x, w = t >> 5, lane = t & 31;
    const int g = lane >> 2, tg = lane & 3;
    const int b = blockIdx.y, n0 = blockIdx.x * 128;

    {
        const float4* sh = (const float4*)(g_An_hi + ((size_t)b * NN + n0) * CP);
        const float4* sl = (const float4*)(g_An_lo + ((size_t)b * NN + n0) * CP);
#pragma unroll
        for (int j = 0; j < 4; j++) {
            int li = t + j * 256, row = li >> 3, ch = li & 7;
            *(float4*)(smc + SM_APEH + row * PITA + ch * 16) = sh[li];
            *(float4*)(smc + SM_APEL + row * PITA + ch * 16) = sl[li];
        }
    }

    auto issue_tile = [&](int mt, int s) {
        int m0 = mt * 128;
        uint32_t ub = sb + SM_STG + s * SSTR;
#pragma unroll
        for (int j = 0; j < 4; j++) {
            int li = t + j * 256, row = li >> 3, ch = li & 7;
            cp16(ub + row * PITA + ch * 16,
                 g_U_hi + ((size_t)b * NN + m0 + row) * CP + ch * 8);
            cp16(ub + OFF_UL + row * PITA + ch * 16,
                 g_U_lo + ((size_t)b * NN + m0 + row) * CP + ch * 8);
        }
#pragma unroll
        for (int j = 0; j < 4; j++) {
            int li = t + j * 256, row = li >> 4, ch = li & 15;
            cp16(ub + OFF_KH + row * PITK + ch * 16,
                 g_Bk_hi + (size_t)(b * CP + row) * NN + m0 + ch * 8);
            cp16(ub + OFF_KL + row * PITK + ch * 16,
                 g_Bk_lo + (size_t)(b * CP + row) * NN + m0 + ch * 8);
        }
    };

    issue_tile(0, 0);
    CP_COMMIT();

    float zacc[8][4];
#pragma unroll
    for (int cf = 0; cf < 8; cf++)
#pragma unroll
        for (int e = 0; e < 4; e++) zacc[cf][e] = 0.0f;
    float mrun0 = -1e30f, mrun1 = -1e30f, lrun0 = 0.0f, lrun1 = 0.0f;

    for (int mt = 0; mt < 16; mt++) {
        if (mt < 15) { issue_tile(mt + 1, (mt + 1) & 1); CP_COMMIT(); CP_WAIT1(); }
        else CP_WAIT0();
        __syncthreads();

        const char* UB = smc + SM_STG + (size_t)(mt & 1) * SSTR;

        float sfr[16][4];
#pragma unroll
        for (int mf = 0; mf < 16; mf++)
#pragma unroll
            for (int e = 0; e < 4; e++) sfr[mf][e] = 0.0f;

#pragma unroll
        for (int ks = 0; ks < 4; ks++) {
            uint32_t abase = (uint32_t)((w * 16 + g) * PITA + (ks * 16 + tg * 2) * 2);
            uint32_t ah[4], al_[4];
            ah[0]  = *(const uint32_t*)(smc + SM_APEH + abase);
            ah[1]  = *(const uint32_t*)(smc + SM_APEH + abase + 8 * PITA);
            ah[2]  = *(const uint32_t*)(smc + SM_APEH + abase + 16);
            ah[3]  = *(const uint32_t*)(smc + SM_APEH + abase + 8 * PITA + 16);
            al_[0] = *(const uint32_t*)(smc + SM_APEL + abase);
            al_[1] = *(const uint32_t*)(smc + SM_APEL + abase + 8 * PITA);
            al_[2] = *(const uint32_t*)(smc + SM_APEL + abase + 16);
            al_[3] = *(const uint32_t*)(smc + SM_APEL + abase + 8 * PITA + 16);
#pragma unroll
            for (int mf = 0; mf < 16; mf++) {
                uint32_t bbase = (uint32_t)((mf * 8 + g) * PITA + (ks * 16 + tg * 2) * 2);
                uint32_t bh[2] = { *(const uint32_t*)(UB + bbase),
                                   *(const uint32_t*)(UB + bbase + 16) };
                uint32_t bl[2] = { *(const uint32_t*)(UB + OFF_UL + bbase),
                                   *(const uint32_t*)(UB + OFF_UL + bbase + 16) };
                mma16816(sfr[mf], ah, bh);
                mma16816(sfr[mf], ah, bl);
                mma16816(sfr[mf], al_, bh);
            }
        }

        float tm0 = -1e30f, tm1 = -1e30f;
#pragma unroll
        for (int mf = 0; mf < 16; mf++) {
            tm0 = fmaxf(tm0, fmaxf(sfr[mf][0], sfr[mf][1]));
            tm1 = fmaxf(tm1, fmaxf(sfr[mf][2], sfr[mf][3]));
        }
        tm0 = fmaxf(tm0, __shfl_xor_sync(0xffffffffu, tm0, 1));
        tm0 = fmaxf(tm0, __shfl_xor_sync(0xffffffffu, tm0, 2));
        tm1 = fmaxf(tm1, __shfl_xor_sync(0xffffffffu, tm1, 1));
        tm1 = fmaxf(tm1, __shfl_xor_sync(0xffffffffu, tm1, 2));
        float nm0 = fmaxf(mrun0, tm0), nm1 = fmaxf(mrun1, tm1);
        float al0 = __expf(mrun0 - nm0), al1 = __expf(mrun1 - nm1);
        mrun0 = nm0; mrun1 = nm1;
#pragma unroll
        for (int cf = 0; cf < 8; cf++) {
            zacc[cf][0] *= al0; zacc[cf][1] *= al0;
            zacc[cf][2] *= al1; zacc[cf][3] *= al1;
        }
        lrun0 *= al0; lrun1 *= al1;

        uint32_t ph[16][2], pl[16][2];
        float rs0 = 0.0f, rs1 = 0.0f;
#pragma unroll
        for (int mf = 0; mf < 16; mf++) {
            float p0 = __expf(sfr[mf][0] - nm0), p1 = __expf(sfr[mf][1] - nm0);
            float p2 = __expf(sfr[mf][2] - nm1), p3 = __expf(sfr[mf][3] - nm1);
            rs0 += p0 + p1; rs1 += p2 + p3;
            uint32_t h01 = cvt2(p1, p0);
            uint32_t h23 = cvt2(p3, p2);
            ph[mf][0] = h01; ph[mf][1] = h23;
            float f0 = __uint_as_float(h01 << 16), f1 = __uint_as_float(h01 & 0xffff0000u);
            float f2 = __uint_as_float(h23 << 16), f3 = __uint_as_float(h23 & 0xffff0000u);
            pl[mf][0] = cvt2(p1 - f1, p0 - f0);
            pl[mf][1] = cvt2(p3 - f3, p2 - f2);
        }
        rs0 += __shfl_xor_sync(0xffffffffu, rs0, 1);
        rs0 += __shfl_xor_sync(0xffffffffu, rs0, 2);
        rs1 += __shfl_xor_sync(0xffffffffu, rs1, 1);
        rs1 += __shfl_xor_sync(0xffffffffu, rs1, 2);
        lrun0 += rs0; lrun1 += rs1;

#pragma unroll
        for (int ks = 0; ks < 8; ks++) {
            uint32_t aph[4] = { ph[2 * ks][0], ph[2 * ks][1], ph[2 * ks + 1][0], ph[2 * ks + 1][1] };
            uint32_t apl[4] = { pl[2 * ks][0], pl[2 * ks][1], pl[2 * ks + 1][0], pl[2 * ks + 1][1] };
#pragma unroll
            for (int cf = 0; cf < 8; cf++) {
                uint32_t bb = (uint32_t)((cf * 8 + g) * PITK + (ks * 16 + tg * 2) * 2);
                uint32_t kh[2] = { *(const uint32_t*)(UB + OFF_KH + bb),
                                   *(const uint32_t*)(UB + OFF_KH + bb + 16) };
                uint32_t kl[2] = { *(const uint32_t*)(UB + OFF_KL + bb),
                                   *(const uint32_t*)(UB + OFF_KL + bb + 16) };
                mma16816(zacc[cf], aph, kh);
                mma16816(zacc[cf], apl, kh);
                mma16816(zacc[cf], aph, kl);
            }
        }
        __syncthreads();
    }

    // ---- epilogue: normalize, split to bf16 hi/lo, write Z [n][c] ----
    float inv0 = 1.0f / lrun0, inv1 = 1.0f / lrun1;
    int nl0 = n0 + w * 16 + g, nl1 = nl0 + 8;
    __nv_bfloat16* Zh0 = g_Zh + ((size_t)b * NN + nl0) * CP;
    __nv_bfloat16* Zl0 = g_Zl + ((size_t)b * NN + nl0) * CP;
    __nv_bfloat16* Zh1 = g_Zh + ((size_t)b * NN + nl1) * CP;
    __nv_bfloat16* Zl1 = g_Zl + ((size_t)b * NN + nl1) * CP;
#pragma unroll
    for (int cf = 0; cf < 8; cf++) {
        int c0 = cf * 8 + tg * 2;
        float v0 = zacc[cf][0] * inv0, v1 = zacc[cf][1] * inv0;
        float v2 = zacc[cf][2] * inv1, v3 = zacc[cf][3] * inv1;
        uint32_t h01 = cvt2(v1, v0);
        uint32_t h23 = cvt2(v3, v2);
        float f0 = __uint_as_float(h01 << 16), f1 = __uint_as_float(h01 & 0xffff0000u);
        float f2 = __uint_as_float(h23 << 16), f3 = __uint_as_float(h23 & 0xffff0000u);
        *reinterpret_cast<uint32_t*>(Zh0 + c0) = h01;
        *reinterpret_cast<uint32_t*>(Zl0 + c0) = cvt2(v1 - f1, v0 - f0);
        *reinterpret_cast<uint32_t*>(Zh1 + c0) = h23;
        *reinterpret_cast<uint32_t*>(Zl1 + c0) = cvt2(v3 - f3, v2 - f2);
    }
}

// ---------------- 4. tensor-core output GEMM with smem-staged stores ----------------
#define GP_WVH 0
#define GP_WVL 18432
#define GP_ZH  36864
#define GP_ZL  55296
#define GP_TOT 73728
#define STP 132                          // staging pitch (floats)

__global__ void __launch_bounds__(256, 1) gemm_out_tc(float* __restrict__ Out) {
    extern __shared__ char sm2[];
    int b = blockIdx.z, d0 = blockIdx.y * 128, n0 = blockIdx.x * 128;
    int t = threadIdx.x, w = t >> 5, lane = t & 31;
    int g = lane >> 2, tg = lane & 3;

#pragma unroll
    for (int j = 0; j < 4; j++) {
        int li = t + j * 256, row = li >> 3, ch = li & 7;
        *(float4*)(sm2 + GP_WVH + row * PITA + ch * 16) =
            *(const float4*)(g_Wvh + (size_t)(d0 + row) * CP + ch * 8);
        *(float4*)(sm2 + GP_WVL + row * PITA + ch * 16) =
            *(const float4*)(g_Wvl + (size_t)(d0 + row) * CP + ch * 8);
        *(float4*)(sm2 + GP_ZH + row * PITA + ch * 16) =
            *(const float4*)(g_Zh + ((size_t)b * NN + n0 + row) * CP + ch * 8);
        *(float4*)(sm2 + GP_ZL + row * PITA + ch * 16) =
            *(const float4*)(g_Zl + ((size_t)b * NN + n0 + row) * CP + ch * 8);
    }
    __syncthreads();

    float acc[16][4];
#pragma unroll
    for (int nf = 0; nf < 16; nf++)
#pragma unroll
        for (int e = 0; e < 4; e++) acc[nf][e] = 0.0f;

#pragma unroll
    for (int ks = 0; ks < 4; ks++) {
        uint32_t abase = (uint32_t)((w * 16 + g) * PITA + (ks * 16 + tg * 2) * 2);
        uint32_t ah[4], al_[4];
        ah[0]  = *(const uint32_t*)(sm2 + GP_WVH + abase);
        ah[1]  = *(const uint32_t*)(sm2 + GP_WVH + abase + 8 * PITA);
        ah[2]  = *(const uint32_t*)(sm2 + GP_WVH + abase + 16);
        ah[3]  = *(const uint32_t*)(sm2 + GP_WVH + abase + 8 * PITA + 16);
        al_[0] = *(const uint32_t*)(sm2 + GP_WVL + abase);
        al_[1] = *(const uint32_t*)(sm2 + GP_WVL + abase + 8 * PITA);
        al_[2] = *(const uint32_t*)(sm2 + GP_WVL + abase + 16);
        al_[3] = *(const uint32_t*)(sm2 + GP_WVL + abase + 8 * PITA + 16);
#pragma unroll
        for (int nf = 0; nf < 16; nf++) {
            uint32_t bbase = (uint32_t)((nf * 8 + g) * PITA + (ks * 16 + tg * 2) * 2);
            uint32_t bh[2] = { *(const uint32_t*)(sm2 + GP_ZH + bbase),
                               *(const uint32_t*)(sm2 + GP_ZH + bbase + 16) };
            uint32_t bl[2] = { *(const uint32_t*)(sm2 + GP_ZL + bbase),
                               *(const uint32_t*)(sm2 + GP_ZL + bbase + 16) };
            mma16816(acc[nf], ah, bh);
            mma16816(acc[nf], ah, bl);
            mma16816(acc[nf], al_, bh);
        }
    }

    // stage to smem (reuse operand area), then coalesced f32 writes
    __syncthreads();
    float* stg = (float*)sm2;
    int r0 = w * 16 + g;
#pragma unroll
    for (int nf = 0; nf < 16; nf++) {
        int c = nf * 8 + tg * 2;
        *(float2*)(stg + r0 * STP + c)       = make_float2(acc[nf][0], acc[nf][1]);
        *(float2*)(stg + (r0 + 8) * STP + c) = make_float2(acc[nf][2], acc[nf][3]);
    }
    __syncthreads();

    float* Op = Out + (size_t)b * DD * NN + n0;
#pragma unroll
    for (int j = 0; j < 16; j++) {
        int idx = t + j * 256;
        int row = idx >> 5, c4 = (idx & 31) * 4;
        *reinterpret_cast<float4*>(Op + (size_t)(d0 + row) * NN + c4) =
            *reinterpret_cast<const float4*>(stg + row * STP + c4);
    }
}

// ---------------------------------------------------------------------------
extern "C" void kernel_launch(void* const* d_in, const int* in_sizes, int n_in,
                              void* d_out, int out_size) {
    const float* pos = (const float*)d_in[0];
    const float* Wq  = (const float*)d_in[1];
    const float* bq  = (const float*)d_in[2];
    const float* Wk  = (const float*)d_in[3];
    const float* bk  = (const float*)d_in[4];
    const float* Wv  = (const float*)d_in[5];
    const float* bv  = (const float*)d_in[6];
    float* out = (float*)d_out;

    prep_kernel<<<MTBLK + WBLK, 256>>>(Wq, bq, Wk, bk, Wv, bv);
    pe_u_kernel<<<dim3(NN / 128, BB), 256>>>(pos);

    cudaFuncSetAttribute(fused_attn_mma, cudaFuncAttributeMaxDynamicSharedMemorySize, SM_TOT);
    fused_attn_mma<<<dim3(NN / 128, BB), 256, SM_TOT>>>();

    cudaFuncSetAttribute(gemm_out_tc, cudaFuncAttributeMaxDynamicSharedMemorySize, GP_TOT);
    gemm_out_tc<<<dim3(NN / 128, DD / 128, BB), 256, GP_TOT>>>(out);
}

// round 15
// speedup vs baseline: 2.3588x; 1.0251x over previous
#include <cuda_runtime.h>
#include <cuda_bf16.h>
#include <math.h>
#include <stdint.h>

#define BB 8
#define NN 2048
#define DD 384
#define CP 64
#define NF 10

__device__ float g_M [CP * CP];
__device__ __nv_bfloat16 g_Wvh[DD * CP];
__device__ __nv_bfloat16 g_Wvl[DD * CP];
__device__ __nv_bfloat16 g_An_hi[BB * NN * CP];
__device__ __nv_bfloat16 g_An_lo[BB * NN * CP];
__device__ __nv_bfloat16 g_U_hi [BB * NN * CP];
__device__ __nv_bfloat16 g_U_lo [BB * NN * CP];
__device__ __nv_bfloat16 g_Bk_hi[BB * CP * NN];
__device__ __nv_bfloat16 g_Bk_lo[BB * CP * NN];
__device__ __nv_bfloat16 g_Zh[BB * NN * CP];
__device__ __nv_bfloat16 g_Zl[BB * NN * CP];

__device__ __forceinline__ uint32_t smem_u32(const void* p) {
    uint32_t a;
    asm("{ .reg .u64 t; cvta.to.shared.u64 t, %1; cvt.u32.u64 %0, t; }" : "=r"(a) : "l"(p));
    return a;
}
__device__ __forceinline__ void cp16(uint32_t dst, const void* src) {
    asm volatile("cp.async.cg.shared.global [%0], [%1], 16;" :: "r"(dst), "l"(src));
}
#define CP_COMMIT() asm volatile("cp.async.commit_group;" ::: "memory")
#define CP_WAIT1()  asm volatile("cp.async.wait_group 1;" ::: "memory")
#define CP_WAIT0()  asm volatile("cp.async.wait_group 0;" ::: "memory")

__device__ __forceinline__ uint32_t cvt2(float hi, float lo) {
    uint32_t r; asm("cvt.rn.bf16x2.f32 %0, %1, %2;" : "=r"(r) : "f"(hi), "f"(lo)); return r;
}
__device__ __forceinline__ void mma16816(float* d, const uint32_t* a, const uint32_t* b) {
    asm volatile("mma.sync.aligned.m16n8k16.row.col.f32.bf16.bf16.f32 "
        "{%0,%1,%2,%3}, {%4,%5,%6,%7}, {%8,%9}, {%0,%1,%2,%3};"
        : "+f"(d[0]), "+f"(d[1]), "+f"(d[2]), "+f"(d[3])
        : "r"(a[0]), "r"(a[1]), "r"(a[2]), "r"(a[3]), "r"(b[0]), "r"(b[1]));
}

// ---------------- 1. prep: M' (warp per 4x4 tile) + Wv' split ----------------
#define MTBLK 32
#define WBLK ((DD * CP + 255) / 256)
__global__ void __launch_bounds__(256) prep_kernel(
        const float* __restrict__ Wq, const float* __restrict__ bq,
        const float* __restrict__ Wk, const float* __restrict__ bk,
        const float* __restrict__ Wv, const float* __restrict__ bv) {
    int t = threadIdx.x;
    if (blockIdx.x < MTBLK) {
        int w = blockIdx.x * 8 + (t >> 5);
        int wi = w >> 4, wj = w & 15;
        int l = t & 31;
        float acc[4][4];
#pragma unroll
        for (int x = 0; x < 4; x++)
#pragma unroll
            for (int y = 0; y < 4; y++) acc[x][y] = 0.0f;
#pragma unroll
        for (int it = 0; it < 12; it++) {
            int d = l + it * 32;
            float aq[4], ak[4];
#pragma unroll
            for (int x = 0; x < 4; x++) {
                int i = wi * 4 + x;
                aq[x] = (i < 60) ? Wq[d * 60 + i] : ((i == 60) ? bq[d] : 0.0f);
                int j = wj * 4 + x;
                ak[x] = (j < 60) ? Wk[d * 60 + j] : ((j == 60) ? bk[d] : 0.0f);
            }
#pragma unroll
            for (int x = 0; x < 4; x++)
#pragma unroll
                for (int y = 0; y < 4; y++) acc[x][y] = fmaf(aq[x], ak[y], acc[x][y]);
        }
        float scale = sqrtf((float)DD);
#pragma unroll
        for (int x = 0; x < 4; x++)
#pragma unroll
            for (int y = 0; y < 4; y++) {
                float v = acc[x][y];
#pragma unroll
                for (int s = 16; s > 0; s >>= 1) v += __shfl_xor_sync(0xffffffffu, v, s);
                if (l == 0) g_M[(wi * 4 + x) * CP + wj * 4 + y] = v * scale;
            }
    } else {
        int r = (blockIdx.x - MTBLK) * 256 + t;
        if (r < DD * CP) {
            int d = r / CP, c = r % CP;
            float v = (c < 60) ? Wv[d * 60 + c] : ((c == 60) ? bv[d] : 0.0f);
            __nv_bfloat16 h = __float2bfloat16(v);
            g_Wvh[r] = h;
            g_Wvl[r] = __float2bfloat16(v - __bfloat162float(h));
        }
    }
}

// ---------------- 2. fused pe + splits + u-GEMM ----------------
#define BSP 132
__global__ void __launch_bounds__(256) pe_u_kernel(const float* __restrict__ pos) {
    __shared__ float Ms[64][64];
    __shared__ float Bs[64][BSP];
    int b = blockIdx.y, n0 = blockIdx.x * 128, t = threadIdx.x;

#pragma unroll
    for (int j = 0; j < 4; j++) {
        int idx = t + j * 256, row = idx >> 4, c4 = idx & 15;
        *reinterpret_cast<float4*>(&Ms[row][c4 * 4]) =
            *reinterpret_cast<const float4*>(g_M + row * CP + c4 * 4);
    }
    {
        int tok = t >> 1, half = t & 1, n = n0 + tok;
        float x0 = pos[(size_t)b * 3 * NN + n];
        float x1 = pos[(size_t)b * 3 * NN + NN + n];
        float x2 = pos[(size_t)b * 3 * NN + 2 * NN + n];
#pragma unroll
        for (int pp = 0; pp < 15; pp++) {
            int p = 15 * half + pp;
            int coord = p / 10, k = p - coord * 10;
            float x = (coord == 0) ? x0 : ((coord == 1) ? x1 : x2);
            float s, c;
            sincosf(x * (float)(1 << k), &s, &c);
            Bs[coord * 20 + k][tok]      = s;
            Bs[coord * 20 + 10 + k][tok] = c;
        }
        if (half) {
            Bs[60][tok] = 1.0f; Bs[61][tok] = 0.0f;
            Bs[62][tok] = 0.0f; Bs[63][tok] = 0.0f;
        }
    }
    __syncthreads();

    {
        int tk = t & 127, which = t >> 7;
        __nv_bfloat16 tmp[64];
        if (which == 0) {
#pragma unroll
            for (int c = 0; c < 64; c++) tmp[c] = __float2bfloat16(Bs[c][tk]);
        } else {
#pragma unroll
            for (int c = 0; c < 64; c++) {
                float x = Bs[c][tk];
                __nv_bfloat16 h = __float2bfloat16(x);
                tmp[c] = __float2bfloat16(x - __bfloat162float(h));
            }
        }
        float4* d = (float4*)((which ? g_An_lo : g_An_hi) + ((size_t)b * NN + n0 + tk) * CP);
#pragma unroll
        for (int j = 0; j < 8; j++) d[j] = ((float4*)tmp)[j];
    }

#pragma unroll
    for (int j = 0; j < 16; j++) {
        int idx = t + j * 256;
        int ch = idx >> 6, tp = idx & 63;
        float2 v = *reinterpret_cast<float2*>(&Bs[ch][tp * 2]);
        uint32_t hw = cvt2(v.y, v.x);
        float h0 = __uint_as_float(hw << 16);
        float h1 = __uint_as_float(hw & 0xffff0000u);
        uint32_t lw = cvt2(v.y - h1, v.x - h0);
        *reinterpret_cast<uint32_t*>(g_Bk_hi + ((size_t)b * CP + ch) * NN + n0 + tp * 2) = hw;
        *reinterpret_cast<uint32_t*>(g_Bk_lo + ((size_t)b * CP + ch) * NN + n0 + tp * 2) = lw;
    }

    int tx = t & 15, ty = t >> 4;
    float acc[4][8];
#pragma unroll
    for (int j = 0; j < 4; j++)
#pragma unroll
        for (int k = 0; k < 8; k++) acc[j][k] = 0.0f;
#pragma unroll 8
    for (int c = 0; c < 64; c++) {
        float a[4];
#pragma unroll
        for (int j = 0; j < 4; j++) a[j] = Ms[ty * 4 + j][c];
        float4 b0 = *reinterpret_cast<float4*>(&Bs[c][tx * 8]);
        float4 b1 = *reinterpret_cast<float4*>(&Bs[c][tx * 8 + 4]);
        float bb[8] = {b0.x, b0.y, b0.z, b0.w, b1.x, b1.y, b1.z, b1.w};
#pragma unroll
        for (int j = 0; j < 4; j++)
#pragma unroll
            for (int k = 0; k < 8; k++) acc[j][k] = fmaf(a[j], bb[k], acc[j][k]);
    }
#pragma unroll
    for (int k = 0; k < 8; k++) {
        size_t m = (size_t)b * NN + n0 + tx * 8 + k;
        uint32_t h01 = cvt2(acc[1][k], acc[0][k]);
        uint32_t h23 = cvt2(acc[3][k], acc[2][k]);
        float f0 = __uint_as_float(h01 << 16), f1 = __uint_as_float(h01 & 0xffff0000u);
        float f2 = __uint_as_float(h23 << 16), f3 = __uint_as_float(h23 & 0xffff0000u);
        uint32_t l01 = cvt2(acc[1][k] - f1, acc[0][k] - f0);
        uint32_t l23 = cvt2(acc[3][k] - f3, acc[2][k] - f2);
        *reinterpret_cast<uint2*>(g_U_hi + m * CP + ty * 4) = make_uint2(h01, h23);
        *reinterpret_cast<uint2*>(g_U_lo + m * CP + ty * 4) = make_uint2(l01, l23);
    }
}

// ---------------- 3. mma.sync fused flash attention, chunked softmax ----------------
#define PITA 144
#define PITK 272
#define SM_APEH 0
#define SM_APEL 18432
#define SM_STG  36864
#define OFF_UL  18432
#define OFF_KH  36864
#define OFF_KL  54272
#define SSTR    71680
#define SM_TOT  (SM_STG + 2 * SSTR)

__global__ void __launch_bounds__(256, 1) fused_attn_mma() {
    extern __shared__ char smc[];
    uint32_t sb = smem_u32(smc);
    const int t = threadIdx.x, w = t >> 5, lane = t & 31;
    const int g = lane >> 2, tg = lane & 3;
    const int b = blockIdx.y, n0 = blockIdx.x * 128;

    {
        const float4* sh = (const float4*)(g_An_hi + ((size_t)b * NN + n0) * CP);
        const float4* sl = (const float4*)(g_An_lo + ((size_t)b * NN + n0) * CP);
#pragma unroll
        for (int j = 0; j < 4; j++) {
            int li = t + j * 256, row = li >> 3, ch = li & 7;
            *(float4*)(smc + SM_APEH + row * PITA + ch * 16) = sh[li];
            *(float4*)(smc + SM_APEL + row * PITA + ch * 16) = sl[li];
        }
    }

    auto issue_tile = [&](int mt, int s) {
        int m0 = mt * 128;
        uint32_t ub = sb + SM_STG + s * SSTR;
#pragma unroll
        for (int j = 0; j < 4; j++) {
            int li = t + j * 256, row = li >> 3, ch = li & 7;
            cp16(ub + row * PITA + ch * 16,
                 g_U_hi + ((size_t)b * NN + m0 + row) * CP + ch * 8);
            cp16(ub + OFF_UL + row * PITA + ch * 16,
                 g_U_lo + ((size_t)b * NN + m0 + row) * CP + ch * 8);
        }
#pragma unroll
        for (int j = 0; j < 4; j++) {
            int li = t + j * 256, row = li >> 4, ch = li & 15;
            cp16(ub + OFF_KH + row * PITK + ch * 16,
                 g_Bk_hi + (size_t)(b * CP + row) * NN + m0 + ch * 8);
            cp16(ub + OFF_KL + row * PITK + ch * 16,
                 g_Bk_lo + (size_t)(b * CP + row) * NN + m0 + ch * 8);
        }
    };

    issue_tile(0, 0);
    CP_COMMIT();
    __syncthreads();                  // APE visible to all warps

    // ---- preload tile-invariant A fragments into registers ----
    uint32_t AH[4][4], AL[4][4];
#pragma unroll
    for (int ks = 0; ks < 4; ks++) {
        uint32_t abase = (uint32_t)((w * 16 + g) * PITA + (ks * 16 + tg * 2) * 2);
        AH[ks][0] = *(const uint32_t*)(smc + SM_APEH + abase);
        AH[ks][1] = *(const uint32_t*)(smc + SM_APEH + abase + 8 * PITA);
        AH[ks][2] = *(const uint32_t*)(smc + SM_APEH + abase + 16);
        AH[ks][3] = *(const uint32_t*)(smc + SM_APEH + abase + 8 * PITA + 16);
        AL[ks][0] = *(const uint32_t*)(smc + SM_APEL + abase);
        AL[ks][1] = *(const uint32_t*)(smc + SM_APEL + abase + 8 * PITA);
        AL[ks][2] = *(const uint32_t*)(smc + SM_APEL + abase + 16);
        AL[ks][3] = *(const uint32_t*)(smc + SM_APEL + abase + 8 * PITA + 16);
    }

    float zacc[8][4];
#pragma unroll
    for (int cf = 0; cf < 8; cf++)
#pragma unroll
        for (int e = 0; e < 4; e++) zacc[cf][e] = 0.0f;
    float mrun0 = -1e30f, mrun1 = -1e30f, lrun0 = 0.0f, lrun1 = 0.0f;

    for (int mt = 0; mt < 16; mt++) {
        if (mt < 15) { issue_tile(mt + 1, (mt + 1) & 1); CP_COMMIT(); CP_WAIT1(); }
        else CP_WAIT0();
        __syncthreads();

        const char* UB = smc + SM_STG + (size_t)(mt & 1) * SSTR;

        // S chunk: mf in [8c, 8c+8)
        auto s_chunk = [&](float (&sfr)[8][4], int c) {
#pragma unroll
            for (int mf = 0; mf < 8; mf++)
#pragma unroll
                for (int e = 0; e < 4; e++) sfr[mf][e] = 0.0f;
#pragma unroll
            for (int ks = 0; ks < 4; ks++) {
#pragma unroll
                for (int mf = 0; mf < 8; mf++) {
                    uint32_t bbase = (uint32_t)(((c * 8 + mf) * 8 + g) * PITA + (ks * 16 + tg * 2) * 2);
                    uint32_t bh[2] = { *(const uint32_t*)(UB + bbase),
                                       *(const uint32_t*)(UB + bbase + 16) };
                    uint32_t bl[2] = { *(const uint32_t*)(UB + OFF_UL + bbase),
                                       *(const uint32_t*)(UB + OFF_UL + bbase + 16) };
                    mma16816(sfr[mf], AH[ks], bh);
                    mma16816(sfr[mf], AH[ks], bl);
                    mma16816(sfr[mf], AL[ks], bh);
                }
            }
        };

        // online softmax on one chunk: updates mrun/lrun/zacc, emits ph/pl
        auto softmax_chunk = [&](float (&sfr)[8][4], uint32_t (&ph)[8][2], uint32_t (&pl)[8][2]) {
            float tm0 = -1e30f, tm1 = -1e30f;
#pragma unroll
            for (int mf = 0; mf < 8; mf++) {
                tm0 = fmaxf(tm0, fmaxf(sfr[mf][0], sfr[mf][1]));
                tm1 = fmaxf(tm1, fmaxf(sfr[mf][2], sfr[mf][3]));
            }
            tm0 = fmaxf(tm0, __shfl_xor_sync(0xffffffffu, tm0, 1));
            tm0 = fmaxf(tm0, __shfl_xor_sync(0xffffffffu, tm0, 2));
            tm1 = fmaxf(tm1, __shfl_xor_sync(0xffffffffu, tm1, 1));
            tm1 = fmaxf(tm1, __shfl_xor_sync(0xffffffffu, tm1, 2));
            float nm0 = fmaxf(mrun0, tm0), nm1 = fmaxf(mrun1, tm1);
            float al0 = __expf(mrun0 - nm0), al1 = __expf(mrun1 - nm1);
            mrun0 = nm0; mrun1 = nm1;
#pragma unroll
            for (int cf = 0; cf < 8; cf++) {
                zacc[cf][0] *= al0; zacc[cf][1] *= al0;
                zacc[cf][2] *= al1; zacc[cf][3] *= al1;
            }
            float rs0 = 0.0f, rs1 = 0.0f;
#pragma unroll
            for (int mf = 0; mf < 8; mf++) {
                float p0 = __expf(sfr[mf][0] - nm0), p1 = __expf(sfr[mf][1] - nm0);
                float p2 = __expf(sfr[mf][2] - nm1), p3 = __expf(sfr[mf][3] - nm1);
                rs0 += p0 + p1; rs1 += p2 + p3;
                uint32_t h01 = cvt2(p1, p0);
                uint32_t h23 = cvt2(p3, p2);
                ph[mf][0] = h01; ph[mf][1] = h23;
                float f0 = __uint_as_float(h01 << 16), f1 = __uint_as_float(h01 & 0xffff0000u);
                float f2 = __uint_as_float(h23 << 16), f3 = __uint_as_float(h23 & 0xffff0000u);
                pl[mf][0] = cvt2(p1 - f1, p0 - f0);
                pl[mf][1] = cvt2(p3 - f3, p2 - f2);
            }
            rs0 += __shfl_xor_sync(0xffffffffu, rs0, 1);
            rs0 += __shfl_xor_sync(0xffffffffu, rs0, 2);
            rs1 += __shfl_xor_sync(0xffffffffu, rs1, 1);
            rs1 += __shfl_xor_sync(0xffffffffu, rs1, 2);
            lrun0 = lrun0 * al0 + rs0;
            lrun1 = lrun1 * al1 + rs1;
        };

        // Z chunk: keys [64c, 64c+64)
        auto z_chunk = [&](const uint32_t (&ph)[8][2], const uint32_t (&pl)[8][2], int c) {
#pragma unroll
            for (int ks = 0; ks < 4; ks++) {
                uint32_t aph[4] = { ph[2 * ks][0], ph[2 * ks][1], ph[2 * ks + 1][0], ph[2 * ks + 1][1] };
                uint32_t apl[4] = { pl[2 * ks][0], pl[2 * ks][1], pl[2 * ks + 1][0], pl[2 * ks + 1][1] };
#pragma unroll
                for (int cf = 0; cf < 8; cf++) {
                    uint32_t bb = (uint32_t)((cf * 8 + g) * PITK + ((c * 4 + ks) * 16 + tg * 2) * 2);
                    uint32_t kh[2] = { *(const uint32_t*)(UB + OFF_KH + bb),
                                       *(const uint32_t*)(UB + OFF_KH + bb + 16) };
                    uint32_t kl[2] = { *(const uint32_t*)(UB + OFF_KL + bb),
                                       *(const uint32_t*)(UB + OFF_KL + bb + 16) };
                    mma16816(zacc[cf], aph, kh);
                    mma16816(zacc[cf], apl, kh);
                    mma16816(zacc[cf], aph, kl);
                }
            }
        };

        float sfr0[8][4], sfr1[8][4];
        uint32_t ph0[8][2], pl0[8][2], ph1[8][2], pl1[8][2];
        s_chunk(sfr0, 0);
        s_chunk(sfr1, 1);                       // in flight while softmax0 runs
        softmax_chunk(sfr0, ph0, pl0);
        z_chunk(ph0, pl0, 0);                   // in flight while softmax1 runs
        softmax_chunk(sfr1, ph1, pl1);
        z_chunk(ph1, pl1, 1);
        __syncthreads();
    }

    // ---- epilogue: normalize, split to bf16 hi/lo, write Z [n][c] ----
    float inv0 = 1.0f / lrun0, inv1 = 1.0f / lrun1;
    int nl0 = n0 + w * 16 + g, nl1 = nl0 + 8;
    __nv_bfloat16* Zh0 = g_Zh + ((size_t)b * NN + nl0) * CP;
    __nv_bfloat16* Zl0 = g_Zl + ((size_t)b * NN + nl0) * CP;
    __nv_bfloat16* Zh1 = g_Zh + ((size_t)b * NN + nl1) * CP;
    __nv_bfloat16* Zl1 = g_Zl + ((size_t)b * NN + nl1) * CP;
#pragma unroll
    for (int cf = 0; cf < 8; cf++) {
        int c0 = cf * 8 + tg * 2;
        float v0 = zacc[cf][0] * inv0, v1 = zacc[cf][1] * inv0;
        float v2 = zacc[cf][2] * inv1, v3 = zacc[cf][3] * inv1;
        uint32_t h01 = cvt2(v1, v0);
        uint32_t h23 = cvt2(v3, v2);
        float f0 = __uint_as_float(h01 << 16), f1 = __uint_as_float(h01 & 0xffff0000u);
        float f2 = __uint_as_float(h23 << 16), f3 = __uint_as_float(h23 & 0xffff0000u);
        *reinterpret_cast<uint32_t*>(Zh0 + c0) = h01;
        *reinterpret_cast<uint32_t*>(Zl0 + c0) = cvt2(v1 - f1, v0 - f0);
        *reinterpret_cast<uint32_t*>(Zh1 + c0) = h23;
        *reinterpret_cast<uint32_t*>(Zl1 + c0) = cvt2(v3 - f3, v2 - f2);
    }
}

// ---------------- 4. tensor-core output GEMM (R10 version) ----------------
#define GP_WVH 0
#define GP_WVL 18432
#define GP_ZH  36864
#define GP_ZL  55296
#define GP_TOT 73728

__global__ void __launch_bounds__(256, 1) gemm_out_tc(float* __restrict__ Out) {
    extern __shared__ char sm2[];
    int b = blockIdx.z, d0 = blockIdx.y * 128, n0 = blockIdx.x * 128;
    int t = threadIdx.x, w = t >> 5, lane = t & 31;
    int g = lane >> 2, tg = lane & 3;

#pragma unroll
    for (int j = 0; j < 4; j++) {
        int li = t + j * 256, row = li >> 3, ch = li & 7;
        *(float4*)(sm2 + GP_WVH + row * PITA + ch * 16) =
            *(const float4*)(g_Wvh + (size_t)(d0 + row) * CP + ch * 8);
        *(float4*)(sm2 + GP_WVL + row * PITA + ch * 16) =
            *(const float4*)(g_Wvl + (size_t)(d0 + row) * CP + ch * 8);
        *(float4*)(sm2 + GP_ZH + row * PITA + ch * 16) =
            *(const float4*)(g_Zh + ((size_t)b * NN + n0 + row) * CP + ch * 8);
        *(float4*)(sm2 + GP_ZL + row * PITA + ch * 16) =
            *(const float4*)(g_Zl + ((size_t)b * NN + n0 + row) * CP + ch * 8);
    }
    __syncthreads();

    float acc[16][4];
#pragma unroll
    for (int nf = 0; nf < 16; nf++)
#pragma unroll
        for (int e = 0; e < 4; e++) acc[nf][e] = 0.0f;

#pragma unroll
    for (int ks = 0; ks < 4; ks++) {
        uint32_t abase = (uint32_t)((w * 16 + g) * PITA + (ks * 16 + tg * 2) * 2);
        uint32_t ah[4], al_[4];
        ah[0]  = *(const uint32_t*)(sm2 + GP_WVH + abase);
        ah[1]  = *(const uint32_t*)(sm2 + GP_WVH + abase + 8 * PITA);
        ah[2]  = *(const uint32_t*)(sm2 + GP_WVH + abase + 16);
        ah[3]  = *(const uint32_t*)(sm2 + GP_WVH + abase + 8 * PITA + 16);
        al_[0] = *(const uint32_t*)(sm2 + GP_WVL + abase);
        al_[1] = *(const uint32_t*)(sm2 + GP_WVL + abase + 8 * PITA);
        al_[2] = *(const uint32_t*)(sm2 + GP_WVL + abase + 16);
        al_[3] = *(const uint32_t*)(sm2 + GP_WVL + abase + 8 * PITA + 16);
#pragma unroll
        for (int nf = 0; nf < 16; nf++) {
            uint32_t bbase = (uint32_t)((nf * 8 + g) * PITA + (ks * 16 + tg * 2) * 2);
            uint32_t bh[2] = { *(const uint32_t*)(sm2 + GP_ZH + bbase),
                               *(const uint32_t*)(sm2 + GP_ZH + bbase + 16) };
            uint32_t bl[2] = { *(const uint32_t*)(sm2 + GP_ZL + bbase),
                               *(const uint32_t*)(sm2 + GP_ZL + bbase + 16) };
            mma16816(acc[nf], ah, bh);
            mma16816(acc[nf], ah, bl);
            mma16816(acc[nf], al_, bh);
        }
    }

    float* Op = Out + (size_t)b * DD * NN;
    int dd0 = d0 + w * 16 + g, dd1 = dd0 + 8;
#pragma unroll
    for (int nf = 0; nf < 16; nf++) {
        int n = n0 + nf * 8 + tg * 2;
        *reinterpret_cast<float2*>(Op + (size_t)dd0 * NN + n) = make_float2(acc[nf][0], acc[nf][1]);
        *reinterpret_cast<float2*>(Op + (size_t)dd1 * NN + n) = make_float2(acc[nf][2], acc[nf][3]);
    }
}

// ---------------------------------------------------------------------------
extern "C" void kernel_launch(void* const* d_in, const int* in_sizes, int n_in,
                              void* d_out, int out_size) {
    const float* pos = (const float*)d_in[0];
    const float* Wq  = (const float*)d_in[1];
    const float* bq  = (const float*)d_in[2];
    const float* Wk  = (const float*)d_in[3];
    const float* bk  = (const float*)d_in[4];
    const float* Wv  = (const float*)d_in[5];
    const float* bv  = (const float*)d_in[6];
    float* out = (float*)d_out;

    prep_kernel<<<MTBLK + WBLK, 256>>>(Wq, bq, Wk, bk, Wv, bv);
    pe_u_kernel<<<dim3(NN / 128, BB), 256>>>(pos);

    cudaFuncSetAttribute(fused_attn_mma, cudaFuncAttributeMaxDynamicSharedMemorySize, SM_TOT);
    fused_attn_mma<<<dim3(NN / 128, BB), 256, SM_TOT>>>();

    cudaFuncSetAttribute(gemm_out_tc, cudaFuncAttributeMaxDynamicSharedMemorySize, GP_TOT);
    gemm_out_tc<<<dim3(NN / 128, DD / 128, BB), 256, GP_TOT>>>(out);
}

// round 16
// speedup vs baseline: 2.3601x; 1.0006x over previous
#include <cuda_runtime.h>
#include <cuda_bf16.h>
#include <math.h>
#include <stdint.h>

#define BB 8
#define NN 2048
#define DD 384
#define CP 64
#define NF 10

__device__ float g_M [CP * CP];
__device__ __nv_bfloat16 g_Wvh[DD * CP];
__device__ __nv_bfloat16 g_Wvl[DD * CP];
__device__ __nv_bfloat16 g_An_hi[BB * NN * CP];
__device__ __nv_bfloat16 g_An_lo[BB * NN * CP];
__device__ __nv_bfloat16 g_U_hi [BB * NN * CP];
__device__ __nv_bfloat16 g_U_lo [BB * NN * CP];
__device__ __nv_bfloat16 g_Bk_hi[BB * CP * NN];
__device__ __nv_bfloat16 g_Bk_lo[BB * CP * NN];
__device__ __nv_bfloat16 g_Zh[BB * NN * CP];
__device__ __nv_bfloat16 g_Zl[BB * NN * CP];

typedef unsigned long long ull;

__device__ __forceinline__ uint32_t smem_u32(const void* p) {
    uint32_t a;
    asm("{ .reg .u64 t; cvta.to.shared.u64 t, %1; cvt.u32.u64 %0, t; }" : "=r"(a) : "l"(p));
    return a;
}
__device__ __forceinline__ void cp16(uint32_t dst, const void* src) {
    asm volatile("cp.async.cg.shared.global [%0], [%1], 16;" :: "r"(dst), "l"(src));
}
#define CP_COMMIT() asm volatile("cp.async.commit_group;" ::: "memory")
#define CP_WAIT1()  asm volatile("cp.async.wait_group 1;" ::: "memory")
#define CP_WAIT0()  asm volatile("cp.async.wait_group 0;" ::: "memory")

__device__ __forceinline__ uint32_t cvt2(float hi, float lo) {
    uint32_t r; asm("cvt.rn.bf16x2.f32 %0, %1, %2;" : "=r"(r) : "f"(hi), "f"(lo)); return r;
}
__device__ __forceinline__ ull pk2(float lo, float hi) {
    ull d; asm("mov.b64 %0, {%1, %2};" : "=l"(d) : "f"(lo), "f"(hi)); return d;
}
__device__ __forceinline__ void upk2(ull v, float& lo, float& hi) {
    asm("mov.b64 {%0, %1}, %2;" : "=f"(lo), "=f"(hi) : "l"(v));
}
__device__ __forceinline__ ull fma2(ull a, ull b, ull c) {
    ull d; asm("fma.rn.f32x2 %0, %1, %2, %3;" : "=l"(d) : "l"(a), "l"(b), "l"(c)); return d;
}
__device__ __forceinline__ void mma16816(float* d, const uint32_t* a, const uint32_t* b) {
    asm volatile("mma.sync.aligned.m16n8k16.row.col.f32.bf16.bf16.f32 "
        "{%0,%1,%2,%3}, {%4,%5,%6,%7}, {%8,%9}, {%0,%1,%2,%3};"
        : "+f"(d[0]), "+f"(d[1]), "+f"(d[2]), "+f"(d[3])
        : "r"(a[0]), "r"(a[1]), "r"(a[2]), "r"(a[3]), "r"(b[0]), "r"(b[1]));
}

// ---------------- 1. prep: M' (warp per 4x4 tile) + Wv' split ----------------
#define MTBLK 32
#define WBLK ((DD * CP + 255) / 256)
__global__ void __launch_bounds__(256) prep_kernel(
        const float* __restrict__ Wq, const float* __restrict__ bq,
        const float* __restrict__ Wk, const float* __restrict__ bk,
        const float* __restrict__ Wv, const float* __restrict__ bv) {
    int t = threadIdx.x;
    if (blockIdx.x < MTBLK) {
        int w = blockIdx.x * 8 + (t >> 5);
        int wi = w >> 4, wj = w & 15;
        int l = t & 31;
        float acc[4][4];
#pragma unroll
        for (int x = 0; x < 4; x++)
#pragma unroll
            for (int y = 0; y < 4; y++) acc[x][y] = 0.0f;
#pragma unroll
        for (int it = 0; it < 12; it++) {
            int d = l + it * 32;
            float aq[4], ak[4];
#pragma unroll
            for (int x = 0; x < 4; x++) {
                int i = wi * 4 + x;
                aq[x] = (i < 60) ? Wq[d * 60 + i] : ((i == 60) ? bq[d] : 0.0f);
                int j = wj * 4 + x;
                ak[x] = (j < 60) ? Wk[d * 60 + j] : ((j == 60) ? bk[d] : 0.0f);
            }
#pragma unroll
            for (int x = 0; x < 4; x++)
#pragma unroll
                for (int y = 0; y < 4; y++) acc[x][y] = fmaf(aq[x], ak[y], acc[x][y]);
        }
        float scale = sqrtf((float)DD);
#pragma unroll
        for (int x = 0; x < 4; x++)
#pragma unroll
            for (int y = 0; y < 4; y++) {
                float v = acc[x][y];
#pragma unroll
                for (int s = 16; s > 0; s >>= 1) v += __shfl_xor_sync(0xffffffffu, v, s);
                if (l == 0) g_M[(wi * 4 + x) * CP + wj * 4 + y] = v * scale;
            }
    } else {
        int r = (blockIdx.x - MTBLK) * 256 + t;
        if (r < DD * CP) {
            int d = r / CP, c = r % CP;
            float v = (c < 60) ? Wv[d * 60 + c] : ((c == 60) ? bv[d] : 0.0f);
            __nv_bfloat16 h = __float2bfloat16(v);
            g_Wvh[r] = h;
            g_Wvl[r] = __float2bfloat16(v - __bfloat162float(h));
        }
    }
}

// ---------------- 2. fused pe + splits + u-GEMM (f32x2 inner product) ----------------
#define BSP 132
__global__ void __launch_bounds__(256) pe_u_kernel(const float* __restrict__ pos) {
    __shared__ float Ms[64][64];
    __shared__ float Bs[64][BSP];
    int b = blockIdx.y, n0 = blockIdx.x * 128, t = threadIdx.x;

#pragma unroll
    for (int j = 0; j < 4; j++) {
        int idx = t + j * 256, row = idx >> 4, c4 = idx & 15;
        *reinterpret_cast<float4*>(&Ms[row][c4 * 4]) =
            *reinterpret_cast<const float4*>(g_M + row * CP + c4 * 4);
    }
    {
        int tok = t >> 1, half = t & 1, n = n0 + tok;
        float x0 = pos[(size_t)b * 3 * NN + n];
        float x1 = pos[(size_t)b * 3 * NN + NN + n];
        float x2 = pos[(size_t)b * 3 * NN + 2 * NN + n];
#pragma unroll
        for (int pp = 0; pp < 15; pp++) {
            int p = 15 * half + pp;
            int coord = p / 10, k = p - coord * 10;
            float x = (coord == 0) ? x0 : ((coord == 1) ? x1 : x2);
            float s, c;
            sincosf(x * (float)(1 << k), &s, &c);
            Bs[coord * 20 + k][tok]      = s;
            Bs[coord * 20 + 10 + k][tok] = c;
        }
        if (half) {
            Bs[60][tok] = 1.0f; Bs[61][tok] = 0.0f;
            Bs[62][tok] = 0.0f; Bs[63][tok] = 0.0f;
        }
    }
    __syncthreads();

    {
        int tk = t & 127, which = t >> 7;
        __nv_bfloat16 tmp[64];
        if (which == 0) {
#pragma unroll
            for (int c = 0; c < 64; c++) tmp[c] = __float2bfloat16(Bs[c][tk]);
        } else {
#pragma unroll
            for (int c = 0; c < 64; c++) {
                float x = Bs[c][tk];
                __nv_bfloat16 h = __float2bfloat16(x);
                tmp[c] = __float2bfloat16(x - __bfloat162float(h));
            }
        }
        float4* d = (float4*)((which ? g_An_lo : g_An_hi) + ((size_t)b * NN + n0 + tk) * CP);
#pragma unroll
        for (int j = 0; j < 8; j++) d[j] = ((float4*)tmp)[j];
    }

#pragma unroll
    for (int j = 0; j < 16; j++) {
        int idx = t + j * 256;
        int ch = idx >> 6, tp = idx & 63;
        float2 v = *reinterpret_cast<float2*>(&Bs[ch][tp * 2]);
        uint32_t hw = cvt2(v.y, v.x);
        float h0 = __uint_as_float(hw << 16);
        float h1 = __uint_as_float(hw & 0xffff0000u);
        uint32_t lw = cvt2(v.y - h1, v.x - h0);
        *reinterpret_cast<uint32_t*>(g_Bk_hi + ((size_t)b * CP + ch) * NN + n0 + tp * 2) = hw;
        *reinterpret_cast<uint32_t*>(g_Bk_lo + ((size_t)b * CP + ch) * NN + n0 + tp * 2) = lw;
    }

    int tx = t & 15, ty = t >> 4;
    ull acc2[4][4];
#pragma unroll
    for (int j = 0; j < 4; j++)
#pragma unroll
        for (int k4 = 0; k4 < 4; k4++) acc2[j][k4] = 0ULL;
#pragma unroll 8
    for (int c = 0; c < 64; c++) {
        float a[4];
#pragma unroll
        for (int j = 0; j < 4; j++) a[j] = Ms[ty * 4 + j][c];
        const ull* bp = reinterpret_cast<const ull*>(&Bs[c][tx * 8]);
        ull b4[4] = { bp[0], bp[1], bp[2], bp[3] };
#pragma unroll
        for (int j = 0; j < 4; j++) {
            ull aj = pk2(a[j], a[j]);
#pragma unroll
            for (int k4 = 0; k4 < 4; k4++) acc2[j][k4] = fma2(aj, b4[k4], acc2[j][k4]);
        }
    }
    float acc[4][8];
#pragma unroll
    for (int j = 0; j < 4; j++)
#pragma unroll
        for (int k4 = 0; k4 < 4; k4++) upk2(acc2[j][k4], acc[j][2 * k4], acc[j][2 * k4 + 1]);
#pragma unroll
    for (int k = 0; k < 8; k++) {
        size_t m = (size_t)b * NN + n0 + tx * 8 + k;
        uint32_t h01 = cvt2(acc[1][k], acc[0][k]);
        uint32_t h23 = cvt2(acc[3][k], acc[2][k]);
        float f0 = __uint_as_float(h01 << 16), f1 = __uint_as_float(h01 & 0xffff0000u);
        float f2 = __uint_as_float(h23 << 16), f3 = __uint_as_float(h23 & 0xffff0000u);
        uint32_t l01 = cvt2(acc[1][k] - f1, acc[0][k] - f0);
        uint32_t l23 = cvt2(acc[3][k] - f3, acc[2][k] - f2);
        *reinterpret_cast<uint2*>(g_U_hi + m * CP + ty * 4) = make_uint2(h01, h23);
        *reinterpret_cast<uint2*>(g_U_lo + m * CP + ty * 4) = make_uint2(l01, l23);
    }
}

// ---------------- 3. mma.sync fused flash attention (R15 form) ----------------
#define PITA 144
#define PITK 272
#define SM_APEH 0
#define SM_APEL 18432
#define SM_STG  36864
#define OFF_UL  18432
#define OFF_KH  36864
#define OFF_KL  54272
#define SSTR    71680
#define SM_TOT  (SM_STG + 2 * SSTR)

__global__ void __launch_bounds__(256, 1) fused_attn_mma() {
    extern __shared__ char smc[];
    uint32_t sb = smem_u32(smc);
    const int t = threadIdx.x, w = t >> 5, lane = t & 31;
    const int g = lane >> 2, tg = lane & 3;
    const int b = blockIdx.y, n0 = blockIdx.x * 128;

    {
        const float4* sh = (const float4*)(g_An_hi + ((size_t)b * NN + n0) * CP);
        const float4* sl = (const float4*)(g_An_lo + ((size_t)b * NN + n0) * CP);
#pragma unroll
        for (int j = 0; j < 4; j++) {
            int li = t + j * 256, row = li >> 3, ch = li & 7;
            *(float4*)(smc + SM_APEH + row * PITA + ch * 16) = sh[li];
            *(float4*)(smc + SM_APEL + row * PITA + ch * 16) = sl[li];
        }
    }

    auto issue_tile = [&](int mt, int s) {
        int m0 = mt * 128;
        uint32_t ub = sb + SM_STG + s * SSTR;
#pragma unroll
        for (int j = 0; j < 4; j++) {
            int li = t + j * 256, row = li >> 3, ch = li & 7;
            cp16(ub + row * PITA + ch * 16,
                 g_U_hi + ((size_t)b * NN + m0 + row) * CP + ch * 8);
            cp16(ub + OFF_UL + row * PITA + ch * 16,
                 g_U_lo + ((size_t)b * NN + m0 + row) * CP + ch * 8);
        }
#pragma unroll
        for (int j = 0; j < 4; j++) {
            int li = t + j * 256, row = li >> 4, ch = li & 15;
            cp16(ub + OFF_KH + row * PITK + ch * 16,
                 g_Bk_hi + (size_t)(b * CP + row) * NN + m0 + ch * 8);
            cp16(ub + OFF_KL + row * PITK + ch * 16,
                 g_Bk_lo + (size_t)(b * CP + row) * NN + m0 + ch * 8);
        }
    };

    issue_tile(0, 0);
    CP_COMMIT();
    __syncthreads();

    uint32_t AH[4][4], AL[4][4];
#pragma unroll
    for (int ks = 0; ks < 4; ks++) {
        uint32_t abase = (uint32_t)((w * 16 + g) * PITA + (ks * 16 + tg * 2) * 2);
        AH[ks][0] = *(const uint32_t*)(smc + SM_APEH + abase);
        AH[ks][1] = *(const uint32_t*)(smc + SM_APEH + abase + 8 * PITA);
        AH[ks][2] = *(const uint32_t*)(smc + SM_APEH + abase + 16);
        AH[ks][3] = *(const uint32_t*)(smc + SM_APEH + abase + 8 * PITA + 16);
        AL[ks][0] = *(const uint32_t*)(smc + SM_APEL + abase);
        AL[ks][1] = *(const uint32_t*)(smc + SM_APEL + abase + 8 * PITA);
        AL[ks][2] = *(const uint32_t*)(smc + SM_APEL + abase + 16);
        AL[ks][3] = *(const uint32_t*)(smc + SM_APEL + abase + 8 * PITA + 16);
    }

    float zacc[8][4];
#pragma unroll
    for (int cf = 0; cf < 8; cf++)
#pragma unroll
        for (int e = 0; e < 4; e++) zacc[cf][e] = 0.0f;
    float mrun0 = -1e30f, mrun1 = -1e30f, lrun0 = 0.0f, lrun1 = 0.0f;

    for (int mt = 0; mt < 16; mt++) {
        if (mt < 15) { issue_tile(mt + 1, (mt + 1) & 1); CP_COMMIT(); CP_WAIT1(); }
        else CP_WAIT0();
        __syncthreads();

        const char* UB = smc + SM_STG + (size_t)(mt & 1) * SSTR;

        auto s_chunk = [&](float (&sfr)[8][4], int c) {
#pragma unroll
            for (int mf = 0; mf < 8; mf++)
#pragma unroll
                for (int e = 0; e < 4; e++) sfr[mf][e] = 0.0f;
#pragma unroll
            for (int ks = 0; ks < 4; ks++) {
#pragma unroll
                for (int mf = 0; mf < 8; mf++) {
                    uint32_t bbase = (uint32_t)(((c * 8 + mf) * 8 + g) * PITA + (ks * 16 + tg * 2) * 2);
                    uint32_t bh[2] = { *(const uint32_t*)(UB + bbase),
                                       *(const uint32_t*)(UB + bbase + 16) };
                    uint32_t bl[2] = { *(const uint32_t*)(UB + OFF_UL + bbase),
                                       *(const uint32_t*)(UB + OFF_UL + bbase + 16) };
                    mma16816(sfr[mf], AH[ks], bh);
                    mma16816(sfr[mf], AH[ks], bl);
                    mma16816(sfr[mf], AL[ks], bh);
                }
            }
        };

        auto softmax_chunk = [&](float (&sfr)[8][4], uint32_t (&ph)[8][2], uint32_t (&pl)[8][2]) {
            float tm0 = -1e30f, tm1 = -1e30f;
#pragma unroll
            for (int mf = 0; mf < 8; mf++) {
                tm0 = fmaxf(tm0, fmaxf(sfr[mf][0], sfr[mf][1]));
                tm1 = fmaxf(tm1, fmaxf(sfr[mf][2], sfr[mf][3]));
            }
            tm0 = fmaxf(tm0, __shfl_xor_sync(0xffffffffu, tm0, 1));
            tm0 = fmaxf(tm0, __shfl_xor_sync(0xffffffffu, tm0, 2));
            tm1 = fmaxf(tm1, __shfl_xor_sync(0xffffffffu, tm1, 1));
            tm1 = fmaxf(tm1, __shfl_xor_sync(0xffffffffu, tm1, 2));
            float nm0 = fmaxf(mrun0, tm0), nm1 = fmaxf(mrun1, tm1);
            float al0 = __expf(mrun0 - nm0), al1 = __expf(mrun1 - nm1);
            mrun0 = nm0; mrun1 = nm1;
#pragma unroll
            for (int cf = 0; cf < 8; cf++) {
                zacc[cf][0] *= al0; zacc[cf][1] *= al0;
                zacc[cf][2] *= al1; zacc[cf][3] *= al1;
            }
            float rs0 = 0.0f, rs1 = 0.0f;
#pragma unroll
            for (int mf = 0; mf < 8; mf++) {
                float p0 = __expf(sfr[mf][0] - nm0), p1 = __expf(sfr[mf][1] - nm0);
                float p2 = __expf(sfr[mf][2] - nm1), p3 = __expf(sfr[mf][3] - nm1);
                rs0 += p0 + p1; rs1 += p2 + p3;
                uint32_t h01 = cvt2(p1, p0);
                uint32_t h23 = cvt2(p3, p2);
                ph[mf][0] = h01; ph[mf][1] = h23;
                float f0 = __uint_as_float(h01 << 16), f1 = __uint_as_float(h01 & 0xffff0000u);
                float f2 = __uint_as_float(h23 << 16), f3 = __uint_as_float(h23 & 0xffff0000u);
                pl[mf][0] = cvt2(p1 - f1, p0 - f0);
                pl[mf][1] = cvt2(p3 - f3, p2 - f2);
            }
            rs0 += __shfl_xor_sync(0xffffffffu, rs0, 1);
            rs0 += __shfl_xor_sync(0xffffffffu, rs0, 2);
            rs1 += __shfl_xor_sync(0xffffffffu, rs1, 1);
            rs1 += __shfl_xor_sync(0xffffffffu, rs1, 2);
            lrun0 = lrun0 * al0 + rs0;
            lrun1 = lrun1 * al1 + rs1;
        };

        auto z_chunk = [&](const uint32_t (&ph)[8][2], const uint32_t (&pl)[8][2], int c) {
#pragma unroll
            for (int ks = 0; ks < 4; ks++) {
                uint32_t aph[4] = { ph[2 * ks][0], ph[2 * ks][1], ph[2 * ks + 1][0], ph[2 * ks + 1][1] };
                uint32_t apl[4] = { pl[2 * ks][0], pl[2 * ks][1], pl[2 * ks + 1][0], pl[2 * ks + 1][1] };
#pragma unroll
                for (int cf = 0; cf < 8; cf++) {
                    uint32_t bb = (uint32_t)((cf * 8 + g) * PITK + ((c * 4 + ks) * 16 + tg * 2) * 2);
                    uint32_t kh[2] = { *(const uint32_t*)(UB + OFF_KH + bb),
                                       *(const uint32_t*)(UB + OFF_KH + bb + 16) };
                    uint32_t kl[2] = { *(const uint32_t*)(UB + OFF_KL + bb),
                                       *(const uint32_t*)(UB + OFF_KL + bb + 16) };
                    mma16816(zacc[cf], aph, kh);
                    mma16816(zacc[cf], apl, kh);
                    mma16816(zacc[cf], aph, kl);
                }
            }
        };

        float sfr0[8][4], sfr1[8][4];
        uint32_t ph0[8][2], pl0[8][2], ph1[8][2], pl1[8][2];
        s_chunk(sfr0, 0);
        s_chunk(sfr1, 1);
        softmax_chunk(sfr0, ph0, pl0);
        z_chunk(ph0, pl0, 0);
        softmax_chunk(sfr1, ph1, pl1);
        z_chunk(ph1, pl1, 1);
        __syncthreads();
    }

    float inv0 = 1.0f / lrun0, inv1 = 1.0f / lrun1;
    int nl0 = n0 + w * 16 + g, nl1 = nl0 + 8;
    __nv_bfloat16* Zh0 = g_Zh + ((size_t)b * NN + nl0) * CP;
    __nv_bfloat16* Zl0 = g_Zl + ((size_t)b * NN + nl0) * CP;
    __nv_bfloat16* Zh1 = g_Zh + ((size_t)b * NN + nl1) * CP;
    __nv_bfloat16* Zl1 = g_Zl + ((size_t)b * NN + nl1) * CP;
#pragma unroll
    for (int cf = 0; cf < 8; cf++) {
        int c0 = cf * 8 + tg * 2;
        float v0 = zacc[cf][0] * inv0, v1 = zacc[cf][1] * inv0;
        float v2 = zacc[cf][2] * inv1, v3 = zacc[cf][3] * inv1;
        uint32_t h01 = cvt2(v1, v0);
        uint32_t h23 = cvt2(v3, v2);
        float f0 = __uint_as_float(h01 << 16), f1 = __uint_as_float(h01 & 0xffff0000u);
        float f2 = __uint_as_float(h23 << 16), f3 = __uint_as_float(h23 & 0xffff0000u);
        *reinterpret_cast<uint32_t*>(Zh0 + c0) = h01;
        *reinterpret_cast<uint32_t*>(Zl0 + c0) = cvt2(v1 - f1, v0 - f0);
        *reinterpret_cast<uint32_t*>(Zh1 + c0) = h23;
        *reinterpret_cast<uint32_t*>(Zl1 + c0) = cvt2(v3 - f3, v2 - f2);
    }
}

// ---------------- 4. tensor-core output GEMM (2 blocks/SM) ----------------
#define GP_WVH 0
#define GP_WVL 18432
#define GP_ZH  36864
#define GP_ZL  55296
#define GP_TOT 73728

__global__ void __launch_bounds__(256, 2) gemm_out_tc(float* __restrict__ Out) {
    extern __shared__ char sm2[];
    int b = blockIdx.z, d0 = blockIdx.y * 128, n0 = blockIdx.x * 128;
    int t = threadIdx.x, w = t >> 5, lane = t & 31;
    int g = lane >> 2, tg = lane & 3;

#pragma unroll
    for (int j = 0; j < 4; j++) {
        int li = t + j * 256, row = li >> 3, ch = li & 7;
        *(float4*)(sm2 + GP_WVH + row * PITA + ch * 16) =
            *(const float4*)(g_Wvh + (size_t)(d0 + row) * CP + ch * 8);
        *(float4*)(sm2 + GP_WVL + row * PITA + ch * 16) =
            *(const float4*)(g_Wvl + (size_t)(d0 + row) * CP + ch * 8);
        *(float4*)(sm2 + GP_ZH + row * PITA + ch * 16) =
            *(const float4*)(g_Zh + ((size_t)b * NN + n0 + row) * CP + ch * 8);
        *(float4*)(sm2 + GP_ZL + row * PITA + ch * 16) =
            *(const float4*)(g_Zl + ((size_t)b * NN + n0 + row) * CP + ch * 8);
    }
    __syncthreads();

    float acc[16][4];
#pragma unroll
    for (int nf = 0; nf < 16; nf++)
#pragma unroll
        for (int e = 0; e < 4; e++) acc[nf][e] = 0.0f;

#pragma unroll
    for (int ks = 0; ks < 4; ks++) {
        uint32_t abase = (uint32_t)((w * 16 + g) * PITA + (ks * 16 + tg * 2) * 2);
        uint32_t ah[4], al_[4];
        ah[0]  = *(const uint32_t*)(sm2 + GP_WVH + abase);
        ah[1]  = *(const uint32_t*)(sm2 + GP_WVH + abase + 8 * PITA);
        ah[2]  = *(const uint32_t*)(sm2 + GP_WVH + abase + 16);
        ah[3]  = *(const uint32_t*)(sm2 + GP_WVH + abase + 8 * PITA + 16);
        al_[0] = *(const uint32_t*)(sm2 + GP_WVL + abase);
        al_[1] = *(const uint32_t*)(sm2 + GP_WVL + abase + 8 * PITA);
        al_[2] = *(const uint32_t*)(sm2 + GP_WVL + abase + 16);
        al_[3] = *(const uint32_t*)(sm2 + GP_WVL + abase + 8 * PITA + 16);
#pragma unroll
        for (int nf = 0; nf < 16; nf++) {
            uint32_t bbase = (uint32_t)((nf * 8 + g) * PITA + (ks * 16 + tg * 2) * 2);
            uint32_t bh[2] = { *(const uint32_t*)(sm2 + GP_ZH + bbase),
                               *(const uint32_t*)(sm2 + GP_ZH + bbase + 16) };
            uint32_t bl[2] = { *(const uint32_t*)(sm2 + GP_ZL + bbase),
                               *(const uint32_t*)(sm2 + GP_ZL + bbase + 16) };
            mma16816(acc[nf], ah, bh);
            mma16816(acc[nf], ah, bl);
            mma16816(acc[nf], al_, bh);
        }
    }

    float* Op = Out + (size_t)b * DD * NN;
    int dd0 = d0 + w * 16 + g, dd1 = dd0 + 8;
#pragma unroll
    for (int nf = 0; nf < 16; nf++) {
        int n = n0 + nf * 8 + tg * 2;
        *reinterpret_cast<float2*>(Op + (size_t)dd0 * NN + n) = make_float2(acc[nf][0], acc[nf][1]);
        *reinterpret_cast<float2*>(Op + (size_t)dd1 * NN + n) = make_float2(acc[nf][2], acc[nf][3]);
    }
}

// ---------------------------------------------------------------------------
extern "C" void kernel_launch(void* const* d_in, const int* in_sizes, int n_in,
                              void* d_out, int out_size) {
    const float* pos = (const float*)d_in[0];
    const float* Wq  = (const float*)d_in[1];
    const float* bq  = (const float*)d_in[2];
    const float* Wk  = (const float*)d_in[3];
    const float* bk  = (const float*)d_in[4];
    const float* Wv  = (const float*)d_in[5];
    const float* bv  = (const float*)d_in[6];
    float* out = (float*)d_out;

    prep_kernel<<<MTBLK + WBLK, 256>>>(Wq, bq, Wk, bk, Wv, bv);
    pe_u_kernel<<<dim3(NN / 128, BB), 256>>>(pos);

    cudaFuncSetAttribute(fused_attn_mma, cudaFuncAttributeMaxDynamicSharedMemorySize, SM_TOT);
    fused_attn_mma<<<dim3(NN / 128, BB), 256, SM_TOT>>>();

    cudaFuncSetAttribute(gemm_out_tc, cudaFuncAttributeMaxDynamicSharedMemorySize, GP_TOT);
    gemm_out_tc<<<dim3(NN / 128, DD / 128, BB), 256, GP_TOT>>>(out);
}